// round 5
// baseline (speedup 1.0000x reference)
#include <cuda_runtime.h>
#include <math.h>

#define S_TOTAL 13294
#define BATCHN 2
#define MTOT (BATCHN * S_TOTAL)   // 26588
#define DM 256
#define DF 1024

// ---------------- scratch (static device globals; no runtime allocation) -------------
__device__ float g_off[MTOT * DM];
__device__ float g_attn[MTOT * 128];
__device__ float g_val[MTOT * DM];
__device__ float g_ao[MTOT * DM];
__device__ float g_src2[MTOT * DM];
__device__ float g_x[MTOT * DM];
__device__ float g_h1[MTOT * DF];
__device__ float g_ff[MTOT * DM];

// packed fp32x2 FMA: d = a*b + d (per half, rn, bit-exact vs scalar fmaf)
__device__ __forceinline__ void ffma2(float2& d, const float2& a, const float2& b) {
    asm("fma.rn.f32x2 %0, %1, %2, %0;"
        : "+l"(reinterpret_cast<unsigned long long&>(d))
        : "l"(reinterpret_cast<const unsigned long long&>(a)),
          "l"(reinterpret_cast<const unsigned long long&>(b)));
}

// ---------------- SGEMM: C[M,N] = (A [+A2]) @ B[K,N] + bias, optional ReLU -----------
// 128x64 tile, BK=16, 256 threads, 8x4 microtile, f32x2 packed FMA.
template <int RELU, int ADD2>
__global__ void __launch_bounds__(256) sgemm(const float* __restrict__ A,
                                             const float* __restrict__ A2,
                                             const float* __restrict__ B,
                                             const float* __restrict__ bias,
                                             float* __restrict__ C,
                                             int M, int K, int N) {
    __shared__ float As[16][132];  // [k][m], 128 + 4 pad (row stride 528B, 16B-multiple)
    __shared__ float Bs[16][64];   // [k][n]

    const int t = threadIdx.x;
    const int tx = t & 15;         // col group: 4 cols
    const int ty = t >> 4;         // row group: 8 rows
    const int row0 = blockIdx.y * 128;
    const int col0 = blockIdx.x * 64;

    // A tile loaders: 128 rows x 16 cols = 512 float4; 2 per thread
    // idx = t*2 + i -> row = idx>>2, col = (idx&3)*4
    // B tile loaders: 16 rows x 64 cols = 256 float4; 1 per thread
    const int brow = t >> 4;
    const int bcol = (t & 15) << 2;

    float2 acc[4][4];  // acc[p][j]: rows (ty*8+2p, ty*8+2p+1), col tx*4+j
#pragma unroll
    for (int p = 0; p < 4; p++)
#pragma unroll
        for (int j = 0; j < 4; j++) acc[p][j] = make_float2(0.f, 0.f);

    for (int k0 = 0; k0 < K; k0 += 16) {
#pragma unroll
        for (int i = 0; i < 2; i++) {
            int idx = t * 2 + i;
            int ar = idx >> 2;
            int ac = (idx & 3) << 2;
            float4 av = make_float4(0.f, 0.f, 0.f, 0.f);
            if (row0 + ar < M) {
                av = *(const float4*)&A[(size_t)(row0 + ar) * K + k0 + ac];
                if (ADD2) {
                    float4 a2 = *(const float4*)&A2[(size_t)(row0 + ar) * K + k0 + ac];
                    av.x += a2.x; av.y += a2.y; av.z += a2.z; av.w += a2.w;
                }
            }
            As[ac + 0][ar] = av.x;
            As[ac + 1][ar] = av.y;
            As[ac + 2][ar] = av.z;
            As[ac + 3][ar] = av.w;
        }
        *(float4*)&Bs[brow][bcol] = *(const float4*)&B[(size_t)(k0 + brow) * N + col0 + bcol];

        __syncthreads();
#pragma unroll
        for (int k = 0; k < 16; k++) {
            float4 a_lo = *(const float4*)&As[k][ty * 8 + 0];
            float4 a_hi = *(const float4*)&As[k][ty * 8 + 4];
            float4 b4   = *(const float4*)&Bs[k][tx * 4];
            float2 ap[4];
            ap[0] = make_float2(a_lo.x, a_lo.y);
            ap[1] = make_float2(a_lo.z, a_lo.w);
            ap[2] = make_float2(a_hi.x, a_hi.y);
            ap[3] = make_float2(a_hi.z, a_hi.w);
            float2 br[4];
            br[0] = make_float2(b4.x, b4.x);
            br[1] = make_float2(b4.y, b4.y);
            br[2] = make_float2(b4.z, b4.z);
            br[3] = make_float2(b4.w, b4.w);
#pragma unroll
            for (int p = 0; p < 4; p++)
#pragma unroll
                for (int j = 0; j < 4; j++)
                    ffma2(acc[p][j], ap[p], br[j]);
        }
        __syncthreads();
    }

    float4 bb = *(const float4*)&bias[col0 + tx * 4];
#pragma unroll
    for (int p = 0; p < 4; p++) {
#pragma unroll
        for (int half = 0; half < 2; half++) {
            int row = row0 + ty * 8 + p * 2 + half;
            if (row < M) {
                float4 v;
                v.x = (half ? acc[p][0].y : acc[p][0].x) + bb.x;
                v.y = (half ? acc[p][1].y : acc[p][1].x) + bb.y;
                v.z = (half ? acc[p][2].y : acc[p][2].x) + bb.z;
                v.w = (half ? acc[p][3].y : acc[p][3].x) + bb.w;
                if (RELU) {
                    v.x = fmaxf(v.x, 0.f); v.y = fmaxf(v.y, 0.f);
                    v.z = fmaxf(v.z, 0.f); v.w = fmaxf(v.w, 0.f);
                }
                *(float4*)&C[(size_t)row * N + col0 + tx * 4] = v;
            }
        }
    }
}

// ---------------- MSDeformAttn sampling: softmax + bilinear + weighted sum -----------
// One block per (batch,token) row; warp h handles head h; lane = head-dim channel.
// Unconditional clamped gathers with mask-folded weights; 32-bit element offsets.
__global__ void __launch_bounds__(256) msda_sample(
    const float* __restrict__ refp,    // (N, S, 4, 2)
    const float* __restrict__ off,     // (rows, 256) = (h, l, p, 2)
    const float* __restrict__ attnlog, // (rows, 128) = (h, l*4+p)
    const float* __restrict__ value,   // (rows, 8, 32)
    float* __restrict__ out)           // (rows, 256)
{
    const int row = blockIdx.x;        // n*S + s
    const int h = threadIdx.x >> 5;
    const int n = (row >= S_TOTAL) ? 1 : 0;

    // softmax over 16 attention logits (warp-uniform)
    const float* al = attnlog + (size_t)row * 128 + h * 16;
    float l[16];
    float m = -1e30f;
#pragma unroll
    for (int j = 0; j < 16; j++) { l[j] = al[j]; m = fmaxf(m, l[j]); }
    float den = 0.f;
#pragma unroll
    for (int j = 0; j < 16; j++) { l[j] = __expf(l[j] - m); den += l[j]; }
    float inv = 1.f / den;

    const float* offp = off + (size_t)row * 256 + h * 32;
    const float* rp = refp + (size_t)row * 8;
    const float* vp = value + threadIdx.x;   // + h*32 + lane

    float acc = 0.f;
#pragma unroll
    for (int lv = 0; lv < 4; lv++) {
        const int H = (lv == 0) ? 100 : (lv == 1) ? 50 : (lv == 2) ? 25 : 13;
        const int W = H;
        const int start = (lv == 0) ? 0 : (lv == 1) ? 10000 : (lv == 2) ? 12500 : 13125;
        float rx = rp[lv * 2 + 0];
        float ry = rp[lv * 2 + 1];
        int base = n * S_TOTAL + start;
#pragma unroll
        for (int p = 0; p < 4; p++) {
            float ox = offp[(lv * 4 + p) * 2 + 0];
            float oy = offp[(lv * 4 + p) * 2 + 1];
            float x = (rx + ox / (float)W) * (float)W - 0.5f;
            float y = (ry + oy / (float)H) * (float)H - 0.5f;
            float x0f = floorf(x), y0f = floorf(y);
            int x0 = (int)x0f, y0 = (int)y0f;
            int x1 = x0 + 1, y1 = y0 + 1;
            float wx1 = x - x0f, wx0 = 1.f - wx1;
            float wy1 = y - y0f, wy0 = 1.f - wy1;
            float aw = l[lv * 4 + p] * inv;

            // validity masks folded into weights; addresses clamped -> unconditional loads
            float fx0 = ((unsigned)x0 < (unsigned)W) ? 1.f : 0.f;
            float fx1 = ((unsigned)x1 < (unsigned)W) ? 1.f : 0.f;
            float fy0 = ((unsigned)y0 < (unsigned)H) ? 1.f : 0.f;
            float fy1 = ((unsigned)y1 < (unsigned)H) ? 1.f : 0.f;
            int xc0 = min(max(x0, 0), W - 1);
            int xc1 = min(max(x1, 0), W - 1);
            int yc0 = min(max(y0, 0), H - 1);
            int yc1 = min(max(y1, 0), H - 1);

            int r00 = (base + yc0 * W + xc0) << 8;
            int r01 = (base + yc0 * W + xc1) << 8;
            int r10 = (base + yc1 * W + xc0) << 8;
            int r11 = (base + yc1 * W + xc1) << 8;

            float v00 = vp[r00];
            float v01 = vp[r01];
            float v10 = vp[r10];
            float v11 = vp[r11];

            float s = (wy0 * wx0 * fy0 * fx0) * v00
                    + (wy0 * wx1 * fy0 * fx1) * v01
                    + (wy1 * wx0 * fy1 * fx0) * v10
                    + (wy1 * wx1 * fy1 * fx1) * v11;
            acc += aw * s;
        }
    }
    out[(size_t)row * 256 + threadIdx.x] = acc;
}

// ---------------- fused residual add + LayerNorm (C = 256) ---------------------------
__global__ void __launch_bounds__(256) add_ln(const float* __restrict__ a,
                                              const float* __restrict__ b,
                                              const float* __restrict__ g,
                                              const float* __restrict__ be,
                                              float* __restrict__ out) {
    int row = blockIdx.x;
    int t = threadIdx.x;
    float v = a[(size_t)row * 256 + t] + b[(size_t)row * 256 + t];

    __shared__ float red[8];
    __shared__ float stat[2];

    float s = v;
#pragma unroll
    for (int o = 16; o; o >>= 1) s += __shfl_xor_sync(0xffffffffu, s, o);
    if ((t & 31) == 0) red[t >> 5] = s;
    __syncthreads();
    if (t == 0) {
        float tot = 0.f;
        for (int i = 0; i < 8; i++) tot += red[i];
        stat[0] = tot * (1.f / 256.f);
    }
    __syncthreads();
    float mean = stat[0];
    float d = v - mean;

    s = d * d;
#pragma unroll
    for (int o = 16; o; o >>= 1) s += __shfl_xor_sync(0xffffffffu, s, o);
    __syncthreads();
    if ((t & 31) == 0) red[t >> 5] = s;
    __syncthreads();
    if (t == 0) {
        float tot = 0.f;
        for (int i = 0; i < 8; i++) tot += red[i];
        stat[1] = tot * (1.f / 256.f);
    }
    __syncthreads();
    float var = stat[1];

    out[(size_t)row * 256 + t] = d * rsqrtf(var + 1e-5f) * g[t] + be[t];
}

// ---------------- launch -------------------------------------------------------------
extern "C" void kernel_launch(void* const* d_in, const int* in_sizes, int n_in,
                              void* d_out, int out_size) {
    const float* src   = (const float*)d_in[0];
    const float* pos   = (const float*)d_in[1];
    const float* refp  = (const float*)d_in[2];
    // d_in[3] spatial_shapes, d_in[4] level_start_index: static metadata, hardcoded
    const float* W_off  = (const float*)d_in[5];
    const float* b_off  = (const float*)d_in[6];
    const float* W_attn = (const float*)d_in[7];
    const float* b_attn = (const float*)d_in[8];
    const float* W_val  = (const float*)d_in[9];
    const float* b_val  = (const float*)d_in[10];
    const float* W_out  = (const float*)d_in[11];
    const float* b_out  = (const float*)d_in[12];
    const float* W1     = (const float*)d_in[13];
    const float* b1     = (const float*)d_in[14];
    const float* W2     = (const float*)d_in[15];
    const float* b2     = (const float*)d_in[16];
    const float* g1p    = (const float*)d_in[17];
    const float* be1p   = (const float*)d_in[18];
    const float* g2p    = (const float*)d_in[19];
    const float* be2p   = (const float*)d_in[20];
    float* out = (float*)d_out;

    float *offb, *attn, *val, *ao, *src2, *x, *h1, *ff;
    cudaGetSymbolAddress((void**)&offb, g_off);
    cudaGetSymbolAddress((void**)&attn, g_attn);
    cudaGetSymbolAddress((void**)&val, g_val);
    cudaGetSymbolAddress((void**)&ao, g_ao);
    cudaGetSymbolAddress((void**)&src2, g_src2);
    cudaGetSymbolAddress((void**)&x, g_x);
    cudaGetSymbolAddress((void**)&h1, g_h1);
    cudaGetSymbolAddress((void**)&ff, g_ff);

    const int M = MTOT;
    const int mby = (M + 127) / 128;

    // q = src + pos fused into the A-operand of the off/attn projections
    sgemm<0, 1><<<dim3(4, mby), 256>>>(src, pos, W_off, b_off, offb, M, 256, 256);
    sgemm<0, 1><<<dim3(2, mby), 256>>>(src, pos, W_attn, b_attn, attn, M, 256, 128);
    sgemm<0, 0><<<dim3(4, mby), 256>>>(src, nullptr, W_val, b_val, val, M, 256, 256);

    msda_sample<<<M, 256>>>(refp, offb, attn, val, ao);

    sgemm<0, 0><<<dim3(4, mby), 256>>>(ao, nullptr, W_out, b_out, src2, M, 256, 256);
    add_ln<<<M, 256>>>(src, src2, g1p, be1p, x);

    sgemm<1, 0><<<dim3(16, mby), 256>>>(x, nullptr, W1, b1, h1, M, 256, 1024);
    sgemm<0, 0><<<dim3(4, mby), 256>>>(h1, nullptr, W2, b2, ff, M, 1024, 256);
    add_ln<<<M, 256>>>(x, ff, g2p, be2p, out);
}

// round 6
// speedup vs baseline: 1.0504x; 1.0504x over previous
#include <cuda_runtime.h>
#include <math.h>

#define S_TOTAL 13294
#define BATCHN 2
#define MTOT (BATCHN * S_TOTAL)   // 26588
#define DM 256
#define DF 1024

// ---------------- scratch (static device globals; no runtime allocation) -------------
__device__ float g_off[MTOT * DM];
__device__ float g_attn[MTOT * 128];
__device__ float g_val[MTOT * DM];
__device__ float g_ao[MTOT * DM];
__device__ float g_src2[MTOT * DM];
__device__ float g_x[MTOT * DM];
__device__ float g_h1[MTOT * DF];
__device__ float g_ff[MTOT * DM];

// ---------------- tf32 helpers --------------------------------------------------------
__device__ __forceinline__ unsigned cvt_tf32(float x) {
    unsigned r;
    asm("cvt.rna.tf32.f32 %0, %1;" : "=r"(r) : "f"(x));
    return r;
}

__device__ __forceinline__ void mma_tf32(float c[4], const unsigned a[4], const unsigned b[2]) {
    asm("mma.sync.aligned.m16n8k8.row.col.f32.tf32.tf32.f32 "
        "{%0,%1,%2,%3}, {%4,%5,%6,%7}, {%8,%9}, {%0,%1,%2,%3};"
        : "+f"(c[0]), "+f"(c[1]), "+f"(c[2]), "+f"(c[3])
        : "r"(a[0]), "r"(a[1]), "r"(a[2]), "r"(a[3]),
          "r"(b[0]), "r"(b[1]));
}

// ---------------- GEMM: C[M,N] = (A [+A2]) @ B[K,N] + bias, optional ReLU -------------
// 128x128 CTA tile, BK=32, 8 warps (2x4), warp tile 64x32 of m16n8k8 mma.
// 3xTF32 split: near-fp32 accuracy on tensor cores.
template <int RELU, int ADD2>
__global__ void __launch_bounds__(256) tgemm(const float* __restrict__ A,
                                             const float* __restrict__ A2,
                                             const float* __restrict__ B,
                                             const float* __restrict__ bias,
                                             float* __restrict__ C,
                                             int M, int K, int N) {
    __shared__ float As[128][36];   // row-major, stride 36 (conflict-free frags, 16B mult)
    __shared__ float Bs[32][132];   // row-major, stride 132

    const int t = threadIdx.x;
    const int w = t >> 5;
    const int lane = t & 31;
    const int g = lane >> 2;        // group id (0..7)
    const int tg = lane & 3;        // thread in group (0..3)

    const int row0 = blockIdx.y * 128;
    const int col0 = blockIdx.x * 128;
    const int wr = (w >> 2) * 64;   // warp row offset in tile
    const int wc = (w & 3) * 32;    // warp col offset in tile

    float acc[4][4][4];             // [rowtile i][coltile j][c0..c3]
#pragma unroll
    for (int i = 0; i < 4; i++)
#pragma unroll
        for (int j = 0; j < 4; j++)
#pragma unroll
            for (int r = 0; r < 4; r++) acc[i][j][r] = 0.f;

    for (int k0 = 0; k0 < K; k0 += 32) {
        // ---- load A tile: 128x32 = 1024 float4, 4 per thread
#pragma unroll
        for (int i = 0; i < 4; i++) {
            int idx4 = t + i * 256;
            int ar = idx4 >> 3;
            int ac = (idx4 & 7) << 2;
            float4 v = make_float4(0.f, 0.f, 0.f, 0.f);
            int row = row0 + ar;
            if (row < M) {
                v = *(const float4*)&A[(size_t)row * K + k0 + ac];
                if (ADD2) {
                    float4 v2 = *(const float4*)&A2[(size_t)row * K + k0 + ac];
                    v.x += v2.x; v.y += v2.y; v.z += v2.z; v.w += v2.w;
                }
            }
            *(float4*)&As[ar][ac] = v;
        }
        // ---- load B tile: 32x128 = 1024 float4, 4 per thread
#pragma unroll
        for (int i = 0; i < 4; i++) {
            int idx4 = t + i * 256;
            int br = idx4 >> 5;
            int bc = (idx4 & 31) << 2;
            *(float4*)&Bs[br][bc] = *(const float4*)&B[(size_t)(k0 + br) * N + col0 + bc];
        }
        __syncthreads();

#pragma unroll
        for (int ks = 0; ks < 4; ks++) {
            const int k8 = ks * 8;
            unsigned ahi[4][4], alo[4][4];
#pragma unroll
            for (int i = 0; i < 4; i++) {
                int r0 = wr + i * 16;
                float f0 = As[r0 + g][k8 + tg];
                float f1 = As[r0 + g + 8][k8 + tg];
                float f2 = As[r0 + g][k8 + tg + 4];
                float f3 = As[r0 + g + 8][k8 + tg + 4];
                ahi[i][0] = cvt_tf32(f0); alo[i][0] = cvt_tf32(f0 - __uint_as_float(ahi[i][0]));
                ahi[i][1] = cvt_tf32(f1); alo[i][1] = cvt_tf32(f1 - __uint_as_float(ahi[i][1]));
                ahi[i][2] = cvt_tf32(f2); alo[i][2] = cvt_tf32(f2 - __uint_as_float(ahi[i][2]));
                ahi[i][3] = cvt_tf32(f3); alo[i][3] = cvt_tf32(f3 - __uint_as_float(ahi[i][3]));
            }
            unsigned bhi[4][2], blo[4][2];
#pragma unroll
            for (int j = 0; j < 4; j++) {
                int c0 = wc + j * 8;
                float f0 = Bs[k8 + tg][c0 + g];
                float f1 = Bs[k8 + tg + 4][c0 + g];
                bhi[j][0] = cvt_tf32(f0); blo[j][0] = cvt_tf32(f0 - __uint_as_float(bhi[j][0]));
                bhi[j][1] = cvt_tf32(f1); blo[j][1] = cvt_tf32(f1 - __uint_as_float(bhi[j][1]));
            }
#pragma unroll
            for (int i = 0; i < 4; i++)
#pragma unroll
                for (int j = 0; j < 4; j++) {
                    mma_tf32(acc[i][j], ahi[i], blo[j]);
                    mma_tf32(acc[i][j], alo[i], bhi[j]);
                    mma_tf32(acc[i][j], ahi[i], bhi[j]);
                }
        }
        __syncthreads();
    }

    // ---- epilogue: c0,c1 at (row, col..col+1); c2,c3 at (row+8, ...)
#pragma unroll
    for (int i = 0; i < 4; i++) {
#pragma unroll
        for (int j = 0; j < 4; j++) {
            int col = col0 + wc + j * 8 + tg * 2;
            float2 bb = *(const float2*)&bias[col];
            int rowA = row0 + wr + i * 16 + g;
            int rowB = rowA + 8;
            float2 v0, v1;
            v0.x = acc[i][j][0] + bb.x;
            v0.y = acc[i][j][1] + bb.y;
            v1.x = acc[i][j][2] + bb.x;
            v1.y = acc[i][j][3] + bb.y;
            if (RELU) {
                v0.x = fmaxf(v0.x, 0.f); v0.y = fmaxf(v0.y, 0.f);
                v1.x = fmaxf(v1.x, 0.f); v1.y = fmaxf(v1.y, 0.f);
            }
            if (rowA < M) *(float2*)&C[(size_t)rowA * N + col] = v0;
            if (rowB < M) *(float2*)&C[(size_t)rowB * N + col] = v1;
        }
    }
}

// ---------------- MSDeformAttn sampling: softmax + bilinear + weighted sum -----------
// One block per (batch,token) row; warp h handles head h; lane = head-dim channel.
__global__ void __launch_bounds__(256) msda_sample(
    const float* __restrict__ refp,    // (N, S, 4, 2)
    const float* __restrict__ off,     // (rows, 256) = (h, l, p, 2)
    const float* __restrict__ attnlog, // (rows, 128) = (h, l*4+p)
    const float* __restrict__ value,   // (rows, 8, 32)
    float* __restrict__ out)           // (rows, 256)
{
    const int Hs[4]     = {100, 50, 25, 13};
    const int starts[4] = {0, 10000, 12500, 13125};

    int row = blockIdx.x;            // n*S + s
    int h = threadIdx.x >> 5;
    int lane = threadIdx.x & 31;
    int n = (row >= S_TOTAL) ? 1 : 0;

    // softmax over 16 attention logits (warp-uniform, redundant per-lane)
    const float* al = attnlog + (size_t)row * 128 + h * 16;
    float l[16];
    float m = -1e30f;
#pragma unroll
    for (int j = 0; j < 16; j++) { l[j] = al[j]; m = fmaxf(m, l[j]); }
    float den = 0.f;
#pragma unroll
    for (int j = 0; j < 16; j++) { l[j] = __expf(l[j] - m); den += l[j]; }
    float inv = 1.f / den;

    const float* offp = off + (size_t)row * 256 + h * 32;
    const float* rp = refp + (size_t)row * 8;

    float acc = 0.f;
#pragma unroll
    for (int lv = 0; lv < 4; lv++) {
        int H = Hs[lv], W = H;
        float rx = rp[lv * 2 + 0];
        float ry = rp[lv * 2 + 1];
        int base = n * S_TOTAL + starts[lv];
#pragma unroll
        for (int p = 0; p < 4; p++) {
            float ox = offp[(lv * 4 + p) * 2 + 0];
            float oy = offp[(lv * 4 + p) * 2 + 1];
            float x = (rx + ox / (float)W) * (float)W - 0.5f;
            float y = (ry + oy / (float)H) * (float)H - 0.5f;
            float x0f = floorf(x), y0f = floorf(y);
            int x0 = (int)x0f, y0 = (int)y0f;
            int x1 = x0 + 1, y1 = y0 + 1;
            float wx1 = x - x0f, wx0 = 1.f - wx1;
            float wy1 = y - y0f, wy0 = 1.f - wy1;
            float aw = l[lv * 4 + p] * inv;

            float s = 0.f;
            bool y0ok = (y0 >= 0) & (y0 < H);
            bool y1ok = (y1 >= 0) & (y1 < H);
            bool x0ok = (x0 >= 0) & (x0 < W);
            bool x1ok = (x1 >= 0) & (x1 < W);
            if (y0ok & x0ok)
                s += wy0 * wx0 * value[((size_t)(base + y0 * W + x0) * 8 + h) * 32 + lane];
            if (y0ok & x1ok)
                s += wy0 * wx1 * value[((size_t)(base + y0 * W + x1) * 8 + h) * 32 + lane];
            if (y1ok & x0ok)
                s += wy1 * wx0 * value[((size_t)(base + y1 * W + x0) * 8 + h) * 32 + lane];
            if (y1ok & x1ok)
                s += wy1 * wx1 * value[((size_t)(base + y1 * W + x1) * 8 + h) * 32 + lane];
            acc += aw * s;
        }
    }
    out[(size_t)row * 256 + h * 32 + lane] = acc;
}

// ---------------- fused residual add + LayerNorm (C = 256) ---------------------------
__global__ void __launch_bounds__(256) add_ln(const float* __restrict__ a,
                                              const float* __restrict__ b,
                                              const float* __restrict__ g,
                                              const float* __restrict__ be,
                                              float* __restrict__ out) {
    int row = blockIdx.x;
    int t = threadIdx.x;
    float v = a[(size_t)row * 256 + t] + b[(size_t)row * 256 + t];

    __shared__ float red[8];
    __shared__ float stat[2];

    float s = v;
#pragma unroll
    for (int o = 16; o; o >>= 1) s += __shfl_xor_sync(0xffffffffu, s, o);
    if ((t & 31) == 0) red[t >> 5] = s;
    __syncthreads();
    if (t == 0) {
        float tot = 0.f;
        for (int i = 0; i < 8; i++) tot += red[i];
        stat[0] = tot * (1.f / 256.f);
    }
    __syncthreads();
    float mean = stat[0];
    float d = v - mean;

    s = d * d;
#pragma unroll
    for (int o = 16; o; o >>= 1) s += __shfl_xor_sync(0xffffffffu, s, o);
    __syncthreads();
    if ((t & 31) == 0) red[t >> 5] = s;
    __syncthreads();
    if (t == 0) {
        float tot = 0.f;
        for (int i = 0; i < 8; i++) tot += red[i];
        stat[1] = tot * (1.f / 256.f);
    }
    __syncthreads();
    float var = stat[1];

    out[(size_t)row * 256 + t] = d * rsqrtf(var + 1e-5f) * g[t] + be[t];
}

// ---------------- launch -------------------------------------------------------------
extern "C" void kernel_launch(void* const* d_in, const int* in_sizes, int n_in,
                              void* d_out, int out_size) {
    const float* src   = (const float*)d_in[0];
    const float* pos   = (const float*)d_in[1];
    const float* refp  = (const float*)d_in[2];
    // d_in[3] spatial_shapes, d_in[4] level_start_index: static metadata, hardcoded
    const float* W_off  = (const float*)d_in[5];
    const float* b_off  = (const float*)d_in[6];
    const float* W_attn = (const float*)d_in[7];
    const float* b_attn = (const float*)d_in[8];
    const float* W_val  = (const float*)d_in[9];
    const float* b_val  = (const float*)d_in[10];
    const float* W_out  = (const float*)d_in[11];
    const float* b_out  = (const float*)d_in[12];
    const float* W1     = (const float*)d_in[13];
    const float* b1     = (const float*)d_in[14];
    const float* W2     = (const float*)d_in[15];
    const float* b2     = (const float*)d_in[16];
    const float* g1p    = (const float*)d_in[17];
    const float* be1p   = (const float*)d_in[18];
    const float* g2p    = (const float*)d_in[19];
    const float* be2p   = (const float*)d_in[20];
    float* out = (float*)d_out;

    float *offb, *attn, *val, *ao, *src2, *x, *h1, *ff;
    cudaGetSymbolAddress((void**)&offb, g_off);
    cudaGetSymbolAddress((void**)&attn, g_attn);
    cudaGetSymbolAddress((void**)&val, g_val);
    cudaGetSymbolAddress((void**)&ao, g_ao);
    cudaGetSymbolAddress((void**)&src2, g_src2);
    cudaGetSymbolAddress((void**)&x, g_x);
    cudaGetSymbolAddress((void**)&h1, g_h1);
    cudaGetSymbolAddress((void**)&ff, g_ff);

    const int M = MTOT;
    const int mby = (M + 127) / 128;

    // q = src + pos fused into the A-operand of the off/attn projections
    tgemm<0, 1><<<dim3(2, mby), 256>>>(src, pos, W_off, b_off, offb, M, 256, 256);
    tgemm<0, 1><<<dim3(1, mby), 256>>>(src, pos, W_attn, b_attn, attn, M, 256, 128);
    tgemm<0, 0><<<dim3(2, mby), 256>>>(src, nullptr, W_val, b_val, val, M, 256, 256);

    msda_sample<<<M, 256>>>(refp, offb, attn, val, ao);

    tgemm<0, 0><<<dim3(2, mby), 256>>>(ao, nullptr, W_out, b_out, src2, M, 256, 256);
    add_ln<<<M, 256>>>(src, src2, g1p, be1p, x);

    tgemm<1, 0><<<dim3(8, mby), 256>>>(x, nullptr, W1, b1, h1, M, 256, 1024);
    tgemm<0, 0><<<dim3(2, mby), 256>>>(h1, nullptr, W2, b2, ff, M, 1024, 256);
    add_ln<<<M, 256>>>(x, ff, g2p, be2p, out);
}

// round 9
// speedup vs baseline: 1.5391x; 1.4652x over previous
#include <cuda_runtime.h>
#include <cuda_bf16.h>
#include <math.h>
#include <cstdint>

#define S_TOTAL 13294
#define BATCHN 2
#define MTOT (BATCHN * S_TOTAL)   // 26588
#define DM 256
#define DF 1024

// ---------------- scratch (static device globals; no runtime allocation) -------------
__device__ __nv_bfloat16 g_qhi[MTOT * DM], g_qlo[MTOT * DM];     // src+pos split
__device__ __nv_bfloat16 g_shi[MTOT * DM], g_slo[MTOT * DM];     // src split
__device__ float g_offb[MTOT * DM];
__device__ float g_attn[MTOT * 128];
__device__ float g_val[MTOT * DM];
__device__ __nv_bfloat16 g_aohi[MTOT * DM], g_aolo[MTOT * DM];   // attn output split
__device__ float g_src2[MTOT * DM];
__device__ float g_x[MTOT * DM];
__device__ __nv_bfloat16 g_xhi[MTOT * DM], g_xlo[MTOT * DM];
__device__ __nv_bfloat16 g_h1hi[MTOT * DF], g_h1lo[MTOT * DF];
__device__ float g_ff[MTOT * DM];

// transposed + bf16-split weights: [N][K] layout
#define WT_TOTAL 753664
__device__ __nv_bfloat16 g_wt_hi[WT_TOTAL];
__device__ __nv_bfloat16 g_wt_lo[WT_TOTAL];
// offsets: off 0, attn 65536, val 98304, out 163840, W1 229376, W2 491520

// ---------------- helpers -------------------------------------------------------------
__device__ __forceinline__ uint32_t smem_u32(const void* p) {
    uint32_t a;
    asm("{ .reg .u64 t; cvta.to.shared.u64 t, %1; cvt.u32.u64 %0, t; }" : "=r"(a) : "l"(p));
    return a;
}
__device__ __forceinline__ void ldsm_x4(uint32_t (&r)[4], uint32_t addr) {
    asm volatile("ldmatrix.sync.aligned.m8n8.x4.shared.b16 {%0,%1,%2,%3}, [%4];"
                 : "=r"(r[0]), "=r"(r[1]), "=r"(r[2]), "=r"(r[3]) : "r"(addr));
}
__device__ __forceinline__ void mma_bf16(float (&c)[4], const uint32_t (&a)[4],
                                         uint32_t b0, uint32_t b1) {
    asm volatile("mma.sync.aligned.m16n8k16.row.col.f32.bf16.bf16.f32 "
                 "{%0,%1,%2,%3}, {%4,%5,%6,%7}, {%8,%9}, {%0,%1,%2,%3};"
                 : "+f"(c[0]), "+f"(c[1]), "+f"(c[2]), "+f"(c[3])
                 : "r"(a[0]), "r"(a[1]), "r"(a[2]), "r"(a[3]), "r"(b0), "r"(b1));
}
__device__ __forceinline__ void split1(float v, __nv_bfloat16& h, __nv_bfloat16& l) {
    h = __float2bfloat16(v);
    l = __float2bfloat16(v - __bfloat162float(h));
}
__device__ __forceinline__ uint32_t packbf(__nv_bfloat16 a, __nv_bfloat16 b) {
    return (uint32_t)__bfloat16_as_ushort(a) | ((uint32_t)__bfloat16_as_ushort(b) << 16);
}

// ---------------- weight transpose + bf16 split: Wt[n][k] = W[k][n] -------------------
__global__ void convw(const float* __restrict__ W, __nv_bfloat16* __restrict__ hi,
                      __nv_bfloat16* __restrict__ lo, int K, int N) {
    int i = blockIdx.x * blockDim.x + threadIdx.x;
    if (i >= N * K) return;
    int n = i / K, k = i - n * K;
    float x = W[(size_t)k * N + n];
    split1(x, hi[i], lo[i]);
}

// ---------------- activation split: q = src+pos -> hi/lo, src -> hi/lo ----------------
__global__ void qsplit(const float* __restrict__ src, const float* __restrict__ pos,
                       uint2* __restrict__ qhi, uint2* __restrict__ qlo,
                       uint2* __restrict__ shi, uint2* __restrict__ slo, int n4) {
    int i = blockIdx.x * blockDim.x + threadIdx.x;
    if (i >= n4) return;
    float4 s = ((const float4*)src)[i];
    float4 p = ((const float4*)pos)[i];
    float4 q = make_float4(s.x + p.x, s.y + p.y, s.z + p.z, s.w + p.w);
    __nv_bfloat16 h0, h1, h2, h3, l0, l1, l2, l3;
    split1(q.x, h0, l0); split1(q.y, h1, l1); split1(q.z, h2, l2); split1(q.w, h3, l3);
    qhi[i] = make_uint2(packbf(h0, h1), packbf(h2, h3));
    qlo[i] = make_uint2(packbf(l0, l1), packbf(l2, l3));
    split1(s.x, h0, l0); split1(s.y, h1, l1); split1(s.z, h2, l2); split1(s.w, h3, l3);
    shi[i] = make_uint2(packbf(h0, h1), packbf(h2, h3));
    slo[i] = make_uint2(packbf(l0, l1), packbf(l2, l3));
}

// ---------------- bf16 tensor-core GEMM (mma.sync m16n8k16, 3x split) -----------------
// C[M,N] = A @ Wt^T + bias. A hi/lo bf16 [M,K]; Wt hi/lo bf16 [N][K].
// CTA 128x128, BK=32, 8 warps (2x4), warp tile 64x32. smem stride 40 (pad) conflict-free.
#define SA 40
template <int RELU, int SPLITOUT>
__global__ void __launch_bounds__(256, 2)
tgemm(const __nv_bfloat16* __restrict__ Ahi, const __nv_bfloat16* __restrict__ Alo,
      const __nv_bfloat16* __restrict__ Bhi, const __nv_bfloat16* __restrict__ Blo,
      const float* __restrict__ bias, float* __restrict__ Cf,
      __nv_bfloat16* __restrict__ Chi, __nv_bfloat16* __restrict__ Clo,
      int M, int K, int N) {
    __shared__ __nv_bfloat16 sAhi[128 * SA], sAlo[128 * SA];
    __shared__ __nv_bfloat16 sBhi[128 * SA], sBlo[128 * SA];

    const int t = threadIdx.x;
    const int w = t >> 5;
    const int lane = t & 31;
    const int row0 = blockIdx.y * 128;
    const int col0 = blockIdx.x * 128;
    const int wr = (w >> 2) * 64;
    const int wc = (w & 3) * 32;

    const uint32_t uAhi = smem_u32(sAhi), uAlo = smem_u32(sAlo);
    const uint32_t uBhi = smem_u32(sBhi), uBlo = smem_u32(sBlo);

    // ldmatrix per-lane byte offsets
    const uint32_t aOff = (uint32_t)(wr * (SA * 2)) + (lane & 15) * (SA * 2) + ((lane >> 4) << 4);
    const uint32_t bOff = (uint32_t)(wc * (SA * 2)) + ((lane & 7) + ((lane >> 4) << 3)) * (SA * 2)
                        + (((lane >> 3) & 1) << 4);

    float acc[4][4][4];
#pragma unroll
    for (int i = 0; i < 4; i++)
#pragma unroll
        for (int j = 0; j < 4; j++)
#pragma unroll
            for (int r = 0; r < 4; r++) acc[i][j][r] = 0.f;

    const int nk = K >> 5;
    for (int ch = 0; ch < nk; ++ch) {
        const int k0 = ch << 5;
        // ---- global -> smem: A tiles (hi/lo), 128x32 bf16 each
#pragma unroll
        for (int half = 0; half < 2; half++) {
            int idx = t + half * 256;         // 512 uint4 per buffer
            int r = idx >> 2;
            int c8 = (idx & 3) << 3;
            uint4 zh = make_uint4(0, 0, 0, 0), zl = make_uint4(0, 0, 0, 0);
            if (row0 + r < M) {
                size_t src = (size_t)(row0 + r) * K + k0 + c8;
                zh = *(const uint4*)&Ahi[src];
                zl = *(const uint4*)&Alo[src];
            }
            *(uint4*)&sAhi[r * SA + c8] = zh;
            *(uint4*)&sAlo[r * SA + c8] = zl;
        }
        // ---- B tiles: rows n = col0..col0+127
#pragma unroll
        for (int half = 0; half < 2; half++) {
            int idx = t + half * 256;
            int r = idx >> 2;
            int c8 = (idx & 3) << 3;
            size_t src = (size_t)(col0 + r) * K + k0 + c8;
            *(uint4*)&sBhi[r * SA + c8] = *(const uint4*)&Bhi[src];
            *(uint4*)&sBlo[r * SA + c8] = *(const uint4*)&Blo[src];
        }
        __syncthreads();

#pragma unroll
        for (int k16 = 0; k16 < 2; k16++) {
            const uint32_t kb = (uint32_t)(k16 << 5);   // 16 bf16 = 32 bytes
            uint32_t aH[4][4], aL[4][4];
#pragma unroll
            for (int i = 0; i < 4; i++) {
                ldsm_x4(aH[i], uAhi + aOff + i * (16 * SA * 2) + kb);
                ldsm_x4(aL[i], uAlo + aOff + i * (16 * SA * 2) + kb);
            }
#pragma unroll
            for (int jp = 0; jp < 2; jp++) {
                uint32_t bH[4], bL[4];
                ldsm_x4(bH, uBhi + bOff + jp * (16 * SA * 2) + kb);
                ldsm_x4(bL, uBlo + bOff + jp * (16 * SA * 2) + kb);
#pragma unroll
                for (int i = 0; i < 4; i++) {
                    mma_bf16(acc[i][jp * 2 + 0], aH[i], bH[0], bH[1]);
                    mma_bf16(acc[i][jp * 2 + 0], aH[i], bL[0], bL[1]);
                    mma_bf16(acc[i][jp * 2 + 0], aL[i], bH[0], bH[1]);
                    mma_bf16(acc[i][jp * 2 + 1], aH[i], bH[2], bH[3]);
                    mma_bf16(acc[i][jp * 2 + 1], aH[i], bL[2], bL[3]);
                    mma_bf16(acc[i][jp * 2 + 1], aL[i], bH[2], bH[3]);
                }
            }
        }
        __syncthreads();
    }

    // ---- epilogue
#pragma unroll
    for (int i = 0; i < 4; i++) {
#pragma unroll
        for (int j = 0; j < 4; j++) {
            int col = col0 + wc + j * 8 + (lane & 3) * 2;
            float bx = bias[col], by = bias[col + 1];
            int rowA = row0 + wr + i * 16 + (lane >> 2);
            int rowB = rowA + 8;
            float v0 = acc[i][j][0] + bx, v1 = acc[i][j][1] + by;
            float v2 = acc[i][j][2] + bx, v3 = acc[i][j][3] + by;
            if (RELU) {
                v0 = fmaxf(v0, 0.f); v1 = fmaxf(v1, 0.f);
                v2 = fmaxf(v2, 0.f); v3 = fmaxf(v3, 0.f);
            }
            if (SPLITOUT) {
                __nv_bfloat16 h0, h1, l0, l1;
                if (rowA < M) {
                    split1(v0, h0, l0); split1(v1, h1, l1);
                    *(uint32_t*)&Chi[(size_t)rowA * N + col] = packbf(h0, h1);
                    *(uint32_t*)&Clo[(size_t)rowA * N + col] = packbf(l0, l1);
                }
                if (rowB < M) {
                    split1(v2, h0, l0); split1(v3, h1, l1);
                    *(uint32_t*)&Chi[(size_t)rowB * N + col] = packbf(h0, h1);
                    *(uint32_t*)&Clo[(size_t)rowB * N + col] = packbf(l0, l1);
                }
            } else {
                if (rowA < M) *(float2*)&Cf[(size_t)rowA * N + col] = make_float2(v0, v1);
                if (rowB < M) *(float2*)&Cf[(size_t)rowB * N + col] = make_float2(v2, v3);
            }
        }
    }
}

// ---------------- MSDeformAttn sampling; outputs bf16 hi/lo split ---------------------
__global__ void __launch_bounds__(256) msda_sample(
    const float* __restrict__ refp, const float* __restrict__ off,
    const float* __restrict__ attnlog, const float* __restrict__ value,
    __nv_bfloat16* __restrict__ outhi, __nv_bfloat16* __restrict__ outlo) {
    const int Hs[4]     = {100, 50, 25, 13};
    const int starts[4] = {0, 10000, 12500, 13125};

    int row = blockIdx.x;
    int h = threadIdx.x >> 5;
    int lane = threadIdx.x & 31;
    int n = (row >= S_TOTAL) ? 1 : 0;

    const float* al = attnlog + (size_t)row * 128 + h * 16;
    float l[16];
    float m = -1e30f;
#pragma unroll
    for (int j = 0; j < 16; j++) { l[j] = al[j]; m = fmaxf(m, l[j]); }
    float den = 0.f;
#pragma unroll
    for (int j = 0; j < 16; j++) { l[j] = __expf(l[j] - m); den += l[j]; }
    float inv = 1.f / den;

    const float* offp = off + (size_t)row * 256 + h * 32;
    const float* rp = refp + (size_t)row * 8;

    float acc = 0.f;
#pragma unroll
    for (int lv = 0; lv < 4; lv++) {
        int H = Hs[lv], W = H;
        float rx = rp[lv * 2 + 0];
        float ry = rp[lv * 2 + 1];
        int base = n * S_TOTAL + starts[lv];
#pragma unroll
        for (int p = 0; p < 4; p++) {
            float ox = offp[(lv * 4 + p) * 2 + 0];
            float oy = offp[(lv * 4 + p) * 2 + 1];
            float x = (rx + ox / (float)W) * (float)W - 0.5f;
            float y = (ry + oy / (float)H) * (float)H - 0.5f;
            float x0f = floorf(x), y0f = floorf(y);
            int x0 = (int)x0f, y0 = (int)y0f;
            int x1 = x0 + 1, y1 = y0 + 1;
            float wx1 = x - x0f, wx0 = 1.f - wx1;
            float wy1 = y - y0f, wy0 = 1.f - wy1;
            float aw = l[lv * 4 + p] * inv;

            float s = 0.f;
            bool y0ok = (y0 >= 0) & (y0 < H);
            bool y1ok = (y1 >= 0) & (y1 < H);
            bool x0ok = (x0 >= 0) & (x0 < W);
            bool x1ok = (x1 >= 0) & (x1 < W);
            if (y0ok & x0ok)
                s += wy0 * wx0 * value[((size_t)(base + y0 * W + x0) * 8 + h) * 32 + lane];
            if (y0ok & x1ok)
                s += wy0 * wx1 * value[((size_t)(base + y0 * W + x1) * 8 + h) * 32 + lane];
            if (y1ok & x0ok)
                s += wy1 * wx0 * value[((size_t)(base + y1 * W + x0) * 8 + h) * 32 + lane];
            if (y1ok & x1ok)
                s += wy1 * wx1 * value[((size_t)(base + y1 * W + x1) * 8 + h) * 32 + lane];
            acc += aw * s;
        }
    }
    __nv_bfloat16 hh, ll;
    split1(acc, hh, ll);
    size_t oidx = (size_t)row * 256 + h * 32 + lane;
    outhi[oidx] = hh;
    outlo[oidx] = ll;
}

// ---------------- fused residual add + LayerNorm (C=256), optional bf16 split out -----
template <int SPLIT>
__global__ void __launch_bounds__(256) add_ln(const float* __restrict__ a,
                                              const float* __restrict__ b,
                                              const float* __restrict__ g,
                                              const float* __restrict__ be,
                                              float* __restrict__ out,
                                              __nv_bfloat16* __restrict__ ohi,
                                              __nv_bfloat16* __restrict__ olo) {
    int row = blockIdx.x;
    int t = threadIdx.x;
    float v = a[(size_t)row * 256 + t] + b[(size_t)row * 256 + t];

    __shared__ float red[8];
    __shared__ float stat[2];

    float s = v;
#pragma unroll
    for (int o = 16; o; o >>= 1) s += __shfl_xor_sync(0xffffffffu, s, o);
    if ((t & 31) == 0) red[t >> 5] = s;
    __syncthreads();
    if (t == 0) {
        float tot = 0.f;
        for (int i = 0; i < 8; i++) tot += red[i];
        stat[0] = tot * (1.f / 256.f);
    }
    __syncthreads();
    float mean = stat[0];
    float d = v - mean;

    s = d * d;
#pragma unroll
    for (int o = 16; o; o >>= 1) s += __shfl_xor_sync(0xffffffffu, s, o);
    __syncthreads();
    if ((t & 31) == 0) red[t >> 5] = s;
    __syncthreads();
    if (t == 0) {
        float tot = 0.f;
        for (int i = 0; i < 8; i++) tot += red[i];
        stat[1] = tot * (1.f / 256.f);
    }
    __syncthreads();
    float var = stat[1];

    float y = d * rsqrtf(var + 1e-5f) * g[t] + be[t];
    out[(size_t)row * 256 + t] = y;
    if (SPLIT) {
        __nv_bfloat16 hh, ll;
        split1(y, hh, ll);
        ohi[(size_t)row * 256 + t] = hh;
        olo[(size_t)row * 256 + t] = ll;
    }
}

// ---------------- launch -------------------------------------------------------------
extern "C" void kernel_launch(void* const* d_in, const int* in_sizes, int n_in,
                              void* d_out, int out_size) {
    const float* src   = (const float*)d_in[0];
    const float* pos   = (const float*)d_in[1];
    const float* refp  = (const float*)d_in[2];
    const float* W_off  = (const float*)d_in[5];
    const float* b_off  = (const float*)d_in[6];
    const float* W_attn = (const float*)d_in[7];
    const float* b_attn = (const float*)d_in[8];
    const float* W_val  = (const float*)d_in[9];
    const float* b_val  = (const float*)d_in[10];
    const float* W_out  = (const float*)d_in[11];
    const float* b_out  = (const float*)d_in[12];
    const float* W1     = (const float*)d_in[13];
    const float* b1     = (const float*)d_in[14];
    const float* W2     = (const float*)d_in[15];
    const float* b2     = (const float*)d_in[16];
    const float* g1p    = (const float*)d_in[17];
    const float* be1p   = (const float*)d_in[18];
    const float* g2p    = (const float*)d_in[19];
    const float* be2p   = (const float*)d_in[20];
    float* out = (float*)d_out;

    __nv_bfloat16 *qhi, *qlo, *shi, *slo, *aohi, *aolo, *xhi, *xlo, *h1hi, *h1lo;
    float *offb, *attn, *val, *src2, *x, *ff;
    cudaGetSymbolAddress((void**)&qhi, g_qhi);   cudaGetSymbolAddress((void**)&qlo, g_qlo);
    cudaGetSymbolAddress((void**)&shi, g_shi);   cudaGetSymbolAddress((void**)&slo, g_slo);
    cudaGetSymbolAddress((void**)&offb, g_offb); cudaGetSymbolAddress((void**)&attn, g_attn);
    cudaGetSymbolAddress((void**)&val, g_val);
    cudaGetSymbolAddress((void**)&aohi, g_aohi); cudaGetSymbolAddress((void**)&aolo, g_aolo);
    cudaGetSymbolAddress((void**)&src2, g_src2); cudaGetSymbolAddress((void**)&x, g_x);
    cudaGetSymbolAddress((void**)&xhi, g_xhi);   cudaGetSymbolAddress((void**)&xlo, g_xlo);
    cudaGetSymbolAddress((void**)&h1hi, g_h1hi); cudaGetSymbolAddress((void**)&h1lo, g_h1lo);
    cudaGetSymbolAddress((void**)&ff, g_ff);

    __nv_bfloat16 *wh, *wl;
    cudaGetSymbolAddress((void**)&wh, g_wt_hi);
    cudaGetSymbolAddress((void**)&wl, g_wt_lo);
    __nv_bfloat16 *offh = wh + 0,      *offl = wl + 0;
    __nv_bfloat16 *atth = wh + 65536,  *attl = wl + 65536;
    __nv_bfloat16 *valh = wh + 98304,  *vall = wl + 98304;
    __nv_bfloat16 *outh = wh + 163840, *outl = wl + 163840;
    __nv_bfloat16 *w1h  = wh + 229376, *w1l  = wl + 229376;
    __nv_bfloat16 *w2h  = wh + 491520, *w2l  = wl + 491520;

    const int M = MTOT;
    const int mby = (M + 127) / 128;   // 208
    const int n4 = M * DM / 4;

    // weight transpose + split
    convw<<<(65536 + 255) / 256, 256>>>(W_off, offh, offl, 256, 256);
    convw<<<(32768 + 255) / 256, 256>>>(W_attn, atth, attl, 256, 128);
    convw<<<(65536 + 255) / 256, 256>>>(W_val, valh, vall, 256, 256);
    convw<<<(65536 + 255) / 256, 256>>>(W_out, outh, outl, 256, 256);
    convw<<<(262144 + 255) / 256, 256>>>(W1, w1h, w1l, 256, 1024);
    convw<<<(262144 + 255) / 256, 256>>>(W2, w2h, w2l, 1024, 256);

    // activation splits: q = src+pos, src
    qsplit<<<(n4 + 255) / 256, 256>>>(src, pos, (uint2*)qhi, (uint2*)qlo,
                                      (uint2*)shi, (uint2*)slo, n4);

    tgemm<0, 0><<<dim3(2, mby), 256>>>(qhi, qlo, offh, offl, b_off, offb, nullptr, nullptr, M, 256, 256);
    tgemm<0, 0><<<dim3(1, mby), 256>>>(qhi, qlo, atth, attl, b_attn, attn, nullptr, nullptr, M, 256, 128);
    tgemm<0, 0><<<dim3(2, mby), 256>>>(shi, slo, valh, vall, b_val, val, nullptr, nullptr, M, 256, 256);

    msda_sample<<<M, 256>>>(refp, offb, attn, val, aohi, aolo);

    tgemm<0, 0><<<dim3(2, mby), 256>>>(aohi, aolo, outh, outl, b_out, src2, nullptr, nullptr, M, 256, 256);
    add_ln<1><<<M, 256>>>(src, src2, g1p, be1p, x, xhi, xlo);

    tgemm<1, 1><<<dim3(8, mby), 256>>>(xhi, xlo, w1h, w1l, b1, nullptr, h1hi, h1lo, M, 256, 1024);
    tgemm<0, 0><<<dim3(2, mby), 256>>>(h1hi, h1lo, w2h, w2l, b2, ff, nullptr, nullptr, M, 1024, 256);
    add_ln<0><<<M, 256>>>(x, ff, g2p, be2p, out, nullptr, nullptr);
}

// round 10
// speedup vs baseline: 1.9408x; 1.2610x over previous
#include <cuda_runtime.h>
#include <cuda_bf16.h>
#include <math.h>
#include <cstdint>

#define S_TOTAL 13294
#define BATCHN 2
#define MTOT (BATCHN * S_TOTAL)   // 26588
#define DM 256
#define DF 1024

// ---------------- scratch (static device globals; no runtime allocation) -------------
__device__ __nv_bfloat16 g_qhi[MTOT * DM], g_qlo[MTOT * DM];     // src+pos split
__device__ __nv_bfloat16 g_shi[MTOT * DM], g_slo[MTOT * DM];     // src split
__device__ float g_offb[MTOT * DM];
__device__ float g_attn[MTOT * 128];
__device__ float g_val[MTOT * DM];
__device__ __nv_bfloat16 g_aohi[MTOT * DM], g_aolo[MTOT * DM];   // attn output split
__device__ float g_src2[MTOT * DM];
__device__ float g_x[MTOT * DM];
__device__ __nv_bfloat16 g_xhi[MTOT * DM], g_xlo[MTOT * DM];
__device__ __nv_bfloat16 g_h1hi[MTOT * DF], g_h1lo[MTOT * DF];
__device__ float g_ff[MTOT * DM];

// msda precomputed gather tables: per (row, head, point): 4 indices + 4 folded weights
__device__ int4   g_sidx[MTOT * 8 * 16];
__device__ float4 g_sw[MTOT * 8 * 16];

// transposed + bf16-split weights: [N][K] layout
#define WT_TOTAL 753664
__device__ __nv_bfloat16 g_wt_hi[WT_TOTAL];
__device__ __nv_bfloat16 g_wt_lo[WT_TOTAL];
// offsets: off 0, attn 65536, val 98304, out 163840, W1 229376, W2 491520

// ---------------- helpers -------------------------------------------------------------
__device__ __forceinline__ uint32_t smem_u32(const void* p) {
    uint32_t a;
    asm("{ .reg .u64 t; cvta.to.shared.u64 t, %1; cvt.u32.u64 %0, t; }" : "=r"(a) : "l"(p));
    return a;
}
__device__ __forceinline__ void ldsm_x4(uint32_t (&r)[4], uint32_t addr) {
    asm volatile("ldmatrix.sync.aligned.m8n8.x4.shared.b16 {%0,%1,%2,%3}, [%4];"
                 : "=r"(r[0]), "=r"(r[1]), "=r"(r[2]), "=r"(r[3]) : "r"(addr));
}
__device__ __forceinline__ void mma_bf16(float (&c)[4], const uint32_t (&a)[4],
                                         uint32_t b0, uint32_t b1) {
    asm volatile("mma.sync.aligned.m16n8k16.row.col.f32.bf16.bf16.f32 "
                 "{%0,%1,%2,%3}, {%4,%5,%6,%7}, {%8,%9}, {%0,%1,%2,%3};"
                 : "+f"(c[0]), "+f"(c[1]), "+f"(c[2]), "+f"(c[3])
                 : "r"(a[0]), "r"(a[1]), "r"(a[2]), "r"(a[3]), "r"(b0), "r"(b1));
}
__device__ __forceinline__ void split1(float v, __nv_bfloat16& h, __nv_bfloat16& l) {
    h = __float2bfloat16(v);
    l = __float2bfloat16(v - __bfloat162float(h));
}
__device__ __forceinline__ uint32_t packbf(__nv_bfloat16 a, __nv_bfloat16 b) {
    return (uint32_t)__bfloat16_as_ushort(a) | ((uint32_t)__bfloat16_as_ushort(b) << 16);
}
__device__ __forceinline__ void cp16(uint32_t dst, const void* src, bool pred) {
    int sz = pred ? 16 : 0;
    asm volatile("cp.async.cg.shared.global [%0], [%1], 16, %2;"
                 :: "r"(dst), "l"(src), "r"(sz) : "memory");
}
#define CP_COMMIT() asm volatile("cp.async.commit_group;" ::: "memory")
#define CP_WAIT(n)  asm volatile("cp.async.wait_group %0;" :: "n"(n) : "memory")

// ---------------- all weights: transpose + bf16 split in ONE launch -------------------
__global__ void convw_all(const float* __restrict__ W_off, const float* __restrict__ W_attn,
                          const float* __restrict__ W_val, const float* __restrict__ W_out,
                          const float* __restrict__ W1, const float* __restrict__ W2,
                          __nv_bfloat16* __restrict__ hi, __nv_bfloat16* __restrict__ lo) {
    int i = blockIdx.x * blockDim.x + threadIdx.x;
    if (i >= WT_TOTAL) return;
    const float* W;
    int K, N, base;
    if (i < 65536)       { W = W_off;  K = 256;  N = 256;  base = 0; }
    else if (i < 98304)  { W = W_attn; K = 256;  N = 128;  base = 65536; }
    else if (i < 163840) { W = W_val;  K = 256;  N = 256;  base = 98304; }
    else if (i < 229376) { W = W_out;  K = 256;  N = 256;  base = 163840; }
    else if (i < 491520) { W = W1;     K = 256;  N = 1024; base = 229376; }
    else                 { W = W2;     K = 1024; N = 256;  base = 491520; }
    int li = i - base;
    int n = li / K, k = li - n * K;
    float x = W[(size_t)k * N + n];
    split1(x, hi[i], lo[i]);
}

// ---------------- activation split: q = src+pos -> hi/lo, src -> hi/lo ----------------
__global__ void qsplit(const float* __restrict__ src, const float* __restrict__ pos,
                       uint2* __restrict__ qhi, uint2* __restrict__ qlo,
                       uint2* __restrict__ shi, uint2* __restrict__ slo, int n4) {
    int i = blockIdx.x * blockDim.x + threadIdx.x;
    if (i >= n4) return;
    float4 s = ((const float4*)src)[i];
    float4 p = ((const float4*)pos)[i];
    float4 q = make_float4(s.x + p.x, s.y + p.y, s.z + p.z, s.w + p.w);
    __nv_bfloat16 h0, h1, h2, h3, l0, l1, l2, l3;
    split1(q.x, h0, l0); split1(q.y, h1, l1); split1(q.z, h2, l2); split1(q.w, h3, l3);
    qhi[i] = make_uint2(packbf(h0, h1), packbf(h2, h3));
    qlo[i] = make_uint2(packbf(l0, l1), packbf(l2, l3));
    split1(s.x, h0, l0); split1(s.y, h1, l1); split1(s.z, h2, l2); split1(s.w, h3, l3);
    shi[i] = make_uint2(packbf(h0, h1), packbf(h2, h3));
    slo[i] = make_uint2(packbf(l0, l1), packbf(l2, l3));
}

// ---------------- bf16 tensor-core GEMM (mma.sync m16n8k16, 3x split) -----------------
// CTA 128x128, BK=32, 8 warps (2x4), warp tile 64x32. cp.async 2-stage double buffer.
#define SA 40
#define BUF_B   10240           // 128 * SA * 2 bytes
#define STAGE_B 40960           // 4 buffers per stage
#define SMEM_TOT (2 * STAGE_B)  // 81920

template <int RELU, int SPLITOUT>
__global__ void __launch_bounds__(256, 2)
tgemm(const __nv_bfloat16* __restrict__ Ahi, const __nv_bfloat16* __restrict__ Alo,
      const __nv_bfloat16* __restrict__ Bhi, const __nv_bfloat16* __restrict__ Blo,
      const float* __restrict__ bias, float* __restrict__ Cf,
      __nv_bfloat16* __restrict__ Chi, __nv_bfloat16* __restrict__ Clo,
      int M, int K, int N) {
    extern __shared__ char dsm[];
    const uint32_t sb = smem_u32(dsm);

    const int t = threadIdx.x;
    const int w = t >> 5;
    const int lane = t & 31;
    const int row0 = blockIdx.y * 128;
    const int col0 = blockIdx.x * 128;
    const int wr = (w >> 2) * 64;
    const int wc = (w & 3) * 32;

    // ldmatrix per-lane byte offsets (relative to buffer base)
    const uint32_t aOff = (uint32_t)(wr * (SA * 2)) + (lane & 15) * (SA * 2) + ((lane >> 4) << 4);
    const uint32_t bOff = (uint32_t)(wc * (SA * 2)) + ((lane & 7) + ((lane >> 4) << 3)) * (SA * 2)
                        + (((lane >> 3) & 1) << 4);

    float acc[4][4][4];
#pragma unroll
    for (int i = 0; i < 4; i++)
#pragma unroll
        for (int j = 0; j < 4; j++)
#pragma unroll
            for (int r = 0; r < 4; r++) acc[i][j][r] = 0.f;

    const int nk = K >> 5;

    auto load_chunk = [&](int ch) {
        const int k0 = ch << 5;
        const uint32_t st = sb + (uint32_t)(ch & 1) * STAGE_B;
#pragma unroll
        for (int half = 0; half < 2; half++) {
            int q = t + half * 256;           // 0..511 uint4 slots
            int r = q >> 2;
            int c8 = (q & 3) << 3;            // bf16 col: 0,8,16,24
            uint32_t doff = (uint32_t)(r * (SA * 2) + c8 * 2);
            bool okA = (row0 + r) < M;
            size_t sA = (size_t)(row0 + r) * K + k0 + c8;
            cp16(st + 0 * BUF_B + doff, &Ahi[okA ? sA : 0], okA);
            cp16(st + 1 * BUF_B + doff, &Alo[okA ? sA : 0], okA);
            size_t sB = (size_t)(col0 + r) * K + k0 + c8;
            cp16(st + 2 * BUF_B + doff, &Bhi[sB], true);
            cp16(st + 3 * BUF_B + doff, &Blo[sB], true);
        }
        CP_COMMIT();
    };

    load_chunk(0);
    for (int ch = 0; ch < nk; ++ch) {
        if (ch + 1 < nk) {
            load_chunk(ch + 1);
            CP_WAIT(1);
        } else {
            CP_WAIT(0);
        }
        __syncthreads();

        const uint32_t st = sb + (uint32_t)(ch & 1) * STAGE_B;
        const uint32_t uAhi = st, uAlo = st + BUF_B, uBhi = st + 2 * BUF_B, uBlo = st + 3 * BUF_B;
#pragma unroll
        for (int k16 = 0; k16 < 2; k16++) {
            const uint32_t kb = (uint32_t)(k16 << 5);
            uint32_t aH[4][4], aL[4][4];
#pragma unroll
            for (int i = 0; i < 4; i++) {
                ldsm_x4(aH[i], uAhi + aOff + i * (16 * SA * 2) + kb);
                ldsm_x4(aL[i], uAlo + aOff + i * (16 * SA * 2) + kb);
            }
#pragma unroll
            for (int jp = 0; jp < 2; jp++) {
                uint32_t bH[4], bL[4];
                ldsm_x4(bH, uBhi + bOff + jp * (16 * SA * 2) + kb);
                ldsm_x4(bL, uBlo + bOff + jp * (16 * SA * 2) + kb);
#pragma unroll
                for (int i = 0; i < 4; i++) {
                    mma_bf16(acc[i][jp * 2 + 0], aH[i], bH[0], bH[1]);
                    mma_bf16(acc[i][jp * 2 + 0], aH[i], bL[0], bL[1]);
                    mma_bf16(acc[i][jp * 2 + 0], aL[i], bH[0], bH[1]);
                    mma_bf16(acc[i][jp * 2 + 1], aH[i], bH[2], bH[3]);
                    mma_bf16(acc[i][jp * 2 + 1], aH[i], bL[2], bL[3]);
                    mma_bf16(acc[i][jp * 2 + 1], aL[i], bH[2], bH[3]);
                }
            }
        }
        __syncthreads();
    }

    // ---- epilogue
#pragma unroll
    for (int i = 0; i < 4; i++) {
#pragma unroll
        for (int j = 0; j < 4; j++) {
            int col = col0 + wc + j * 8 + (lane & 3) * 2;
            float bx = bias[col], by = bias[col + 1];
            int rowA = row0 + wr + i * 16 + (lane >> 2);
            int rowB = rowA + 8;
            float v0 = acc[i][j][0] + bx, v1 = acc[i][j][1] + by;
            float v2 = acc[i][j][2] + bx, v3 = acc[i][j][3] + by;
            if (RELU) {
                v0 = fmaxf(v0, 0.f); v1 = fmaxf(v1, 0.f);
                v2 = fmaxf(v2, 0.f); v3 = fmaxf(v3, 0.f);
            }
            if (SPLITOUT) {
                __nv_bfloat16 h0, h1, l0, l1;
                if (rowA < M) {
                    split1(v0, h0, l0); split1(v1, h1, l1);
                    *(uint32_t*)&Chi[(size_t)rowA * N + col] = packbf(h0, h1);
                    *(uint32_t*)&Clo[(size_t)rowA * N + col] = packbf(l0, l1);
                }
                if (rowB < M) {
                    split1(v2, h0, l0); split1(v3, h1, l1);
                    *(uint32_t*)&Chi[(size_t)rowB * N + col] = packbf(h0, h1);
                    *(uint32_t*)&Clo[(size_t)rowB * N + col] = packbf(l0, l1);
                }
            } else {
                if (rowA < M) *(float2*)&Cf[(size_t)rowA * N + col] = make_float2(v0, v1);
                if (rowB < M) *(float2*)&Cf[(size_t)rowB * N + col] = make_float2(v2, v3);
            }
        }
    }
}

// ---------------- msda prep: one thread per (row, head) -------------------------------
// Computes softmax + all 16 sample points' clamped indices and mask-folded weights.
__global__ void __launch_bounds__(256) msda_prep(
    const float* __restrict__ refp, const float* __restrict__ off,
    const float* __restrict__ attnlog, int4* __restrict__ sidx, float4* __restrict__ sw) {
    int tid = blockIdx.x * blockDim.x + threadIdx.x;
    if (tid >= MTOT * 8) return;
    int row = tid >> 3, h = tid & 7;
    int n = (row >= S_TOTAL) ? 1 : 0;

    float l[16];
    const float4* al4 = (const float4*)(attnlog + (size_t)row * 128 + h * 16);
#pragma unroll
    for (int j = 0; j < 4; j++) {
        float4 v = al4[j];
        l[j * 4 + 0] = v.x; l[j * 4 + 1] = v.y; l[j * 4 + 2] = v.z; l[j * 4 + 3] = v.w;
    }
    float m = -1e30f;
#pragma unroll
    for (int j = 0; j < 16; j++) m = fmaxf(m, l[j]);
    float den = 0.f;
#pragma unroll
    for (int j = 0; j < 16; j++) { l[j] = __expf(l[j] - m); den += l[j]; }
    float inv = 1.f / den;

    const float2* offp = (const float2*)(off + (size_t)row * 256 + h * 32);
    const float* rp = refp + (size_t)row * 8;

    const int Hs[4]     = {100, 50, 25, 13};
    const int starts[4] = {0, 10000, 12500, 13125};

#pragma unroll
    for (int lv = 0; lv < 4; lv++) {
        int H = Hs[lv], W = H;
        float rx = rp[lv * 2 + 0];
        float ry = rp[lv * 2 + 1];
        int base = n * S_TOTAL + starts[lv];
#pragma unroll
        for (int p = 0; p < 4; p++) {
            float2 o = offp[lv * 4 + p];
            float x = (rx + o.x / (float)W) * (float)W - 0.5f;
            float y = (ry + o.y / (float)H) * (float)H - 0.5f;
            float x0f = floorf(x), y0f = floorf(y);
            int x0 = (int)x0f, y0 = (int)y0f;
            int x1 = x0 + 1, y1 = y0 + 1;
            float wx1 = x - x0f, wx0 = 1.f - wx1;
            float wy1 = y - y0f, wy0 = 1.f - wy1;
            float aw = l[lv * 4 + p] * inv;

            float fx0 = ((unsigned)x0 < (unsigned)W) ? 1.f : 0.f;
            float fx1 = ((unsigned)x1 < (unsigned)W) ? 1.f : 0.f;
            float fy0 = ((unsigned)y0 < (unsigned)H) ? 1.f : 0.f;
            float fy1 = ((unsigned)y1 < (unsigned)H) ? 1.f : 0.f;
            int xc0 = min(max(x0, 0), W - 1);
            int xc1 = min(max(x1, 0), W - 1);
            int yc0 = min(max(y0, 0), H - 1);
            int yc1 = min(max(y1, 0), H - 1);

            int4 idx;
            idx.x = base + yc0 * W + xc0;
            idx.y = base + yc0 * W + xc1;
            idx.z = base + yc1 * W + xc0;
            idx.w = base + yc1 * W + xc1;
            float4 wv;
            wv.x = aw * wy0 * wx0 * fy0 * fx0;
            wv.y = aw * wy0 * wx1 * fy0 * fx1;
            wv.z = aw * wy1 * wx0 * fy1 * fx0;
            wv.w = aw * wy1 * wx1 * fy1 * fx1;
            sidx[(size_t)tid * 16 + lv * 4 + p] = idx;
            sw[(size_t)tid * 16 + lv * 4 + p] = wv;
        }
    }
}

// ---------------- msda gather: block = token row, warp = head, lane = channel ---------
__global__ void __launch_bounds__(256) msda_gather(
    const int4* __restrict__ sidx, const float4* __restrict__ sw,
    const float* __restrict__ value,
    __nv_bfloat16* __restrict__ outhi, __nv_bfloat16* __restrict__ outlo) {
    int row = blockIdx.x;
    int h = threadIdx.x >> 5;
    int lane = threadIdx.x & 31;
    const int4* ip = sidx + ((size_t)row * 8 + h) * 16;
    const float4* wp = sw + ((size_t)row * 8 + h) * 16;
    const float* vp = value + h * 32 + lane;

    float acc = 0.f;
#pragma unroll
    for (int p = 0; p < 16; p++) {
        int4 id = ip[p];
        float4 wv = wp[p];
        acc = fmaf(wv.x, vp[(size_t)id.x << 8], acc);
        acc = fmaf(wv.y, vp[(size_t)id.y << 8], acc);
        acc = fmaf(wv.z, vp[(size_t)id.z << 8], acc);
        acc = fmaf(wv.w, vp[(size_t)id.w << 8], acc);
    }
    __nv_bfloat16 hh, ll;
    split1(acc, hh, ll);
    size_t oidx = (size_t)row * 256 + h * 32 + lane;
    outhi[oidx] = hh;
    outlo[oidx] = ll;
}

// ---------------- fused residual add + LayerNorm (C=256), optional bf16 split out -----
template <int SPLIT>
__global__ void __launch_bounds__(256) add_ln(const float* __restrict__ a,
                                              const float* __restrict__ b,
                                              const float* __restrict__ g,
                                              const float* __restrict__ be,
                                              float* __restrict__ out,
                                              __nv_bfloat16* __restrict__ ohi,
                                              __nv_bfloat16* __restrict__ olo) {
    int row = blockIdx.x;
    int t = threadIdx.x;
    float v = a[(size_t)row * 256 + t] + b[(size_t)row * 256 + t];

    __shared__ float red[8];
    __shared__ float stat[2];

    float s = v;
#pragma unroll
    for (int o = 16; o; o >>= 1) s += __shfl_xor_sync(0xffffffffu, s, o);
    if ((t & 31) == 0) red[t >> 5] = s;
    __syncthreads();
    if (t == 0) {
        float tot = 0.f;
        for (int i = 0; i < 8; i++) tot += red[i];
        stat[0] = tot * (1.f / 256.f);
    }
    __syncthreads();
    float mean = stat[0];
    float d = v - mean;

    s = d * d;
#pragma unroll
    for (int o = 16; o; o >>= 1) s += __shfl_xor_sync(0xffffffffu, s, o);
    __syncthreads();
    if ((t & 31) == 0) red[t >> 5] = s;
    __syncthreads();
    if (t == 0) {
        float tot = 0.f;
        for (int i = 0; i < 8; i++) tot += red[i];
        stat[1] = tot * (1.f / 256.f);
    }
    __syncthreads();
    float var = stat[1];

    float y = d * rsqrtf(var + 1e-5f) * g[t] + be[t];
    out[(size_t)row * 256 + t] = y;
    if (SPLIT) {
        __nv_bfloat16 hh, ll;
        split1(y, hh, ll);
        ohi[(size_t)row * 256 + t] = hh;
        olo[(size_t)row * 256 + t] = ll;
    }
}

// ---------------- launch -------------------------------------------------------------
extern "C" void kernel_launch(void* const* d_in, const int* in_sizes, int n_in,
                              void* d_out, int out_size) {
    const float* src   = (const float*)d_in[0];
    const float* pos   = (const float*)d_in[1];
    const float* refp  = (const float*)d_in[2];
    const float* W_off  = (const float*)d_in[5];
    const float* b_off  = (const float*)d_in[6];
    const float* W_attn = (const float*)d_in[7];
    const float* b_attn = (const float*)d_in[8];
    const float* W_val  = (const float*)d_in[9];
    const float* b_val  = (const float*)d_in[10];
    const float* W_out  = (const float*)d_in[11];
    const float* b_out  = (const float*)d_in[12];
    const float* W1     = (const float*)d_in[13];
    const float* b1     = (const float*)d_in[14];
    const float* W2     = (const float*)d_in[15];
    const float* b2     = (const float*)d_in[16];
    const float* g1p    = (const float*)d_in[17];
    const float* be1p   = (const float*)d_in[18];
    const float* g2p    = (const float*)d_in[19];
    const float* be2p   = (const float*)d_in[20];
    float* out = (float*)d_out;

    __nv_bfloat16 *qhi, *qlo, *shi, *slo, *aohi, *aolo, *xhi, *xlo, *h1hi, *h1lo;
    float *offb, *attn, *val, *src2, *x, *ff;
    int4* sidx;
    float4* sw;
    cudaGetSymbolAddress((void**)&qhi, g_qhi);   cudaGetSymbolAddress((void**)&qlo, g_qlo);
    cudaGetSymbolAddress((void**)&shi, g_shi);   cudaGetSymbolAddress((void**)&slo, g_slo);
    cudaGetSymbolAddress((void**)&offb, g_offb); cudaGetSymbolAddress((void**)&attn, g_attn);
    cudaGetSymbolAddress((void**)&val, g_val);
    cudaGetSymbolAddress((void**)&aohi, g_aohi); cudaGetSymbolAddress((void**)&aolo, g_aolo);
    cudaGetSymbolAddress((void**)&src2, g_src2); cudaGetSymbolAddress((void**)&x, g_x);
    cudaGetSymbolAddress((void**)&xhi, g_xhi);   cudaGetSymbolAddress((void**)&xlo, g_xlo);
    cudaGetSymbolAddress((void**)&h1hi, g_h1hi); cudaGetSymbolAddress((void**)&h1lo, g_h1lo);
    cudaGetSymbolAddress((void**)&ff, g_ff);
    cudaGetSymbolAddress((void**)&sidx, g_sidx);
    cudaGetSymbolAddress((void**)&sw, g_sw);

    __nv_bfloat16 *wh, *wl;
    cudaGetSymbolAddress((void**)&wh, g_wt_hi);
    cudaGetSymbolAddress((void**)&wl, g_wt_lo);
    __nv_bfloat16 *offh = wh + 0,      *offl = wl + 0;
    __nv_bfloat16 *atth = wh + 65536,  *attl = wl + 65536;
    __nv_bfloat16 *valh = wh + 98304,  *vall = wl + 98304;
    __nv_bfloat16 *outh = wh + 163840, *outl = wl + 163840;
    __nv_bfloat16 *w1h  = wh + 229376, *w1l  = wl + 229376;
    __nv_bfloat16 *w2h  = wh + 491520, *w2l  = wl + 491520;

    cudaFuncSetAttribute(tgemm<0, 0>, cudaFuncAttributeMaxDynamicSharedMemorySize, SMEM_TOT);
    cudaFuncSetAttribute(tgemm<1, 1>, cudaFuncAttributeMaxDynamicSharedMemorySize, SMEM_TOT);

    const int M = MTOT;
    const int mby = (M + 127) / 128;   // 208
    const int n4 = M * DM / 4;

    convw_all<<<(WT_TOTAL + 255) / 256, 256>>>(W_off, W_attn, W_val, W_out, W1, W2, wh, wl);
    qsplit<<<(n4 + 255) / 256, 256>>>(src, pos, (uint2*)qhi, (uint2*)qlo,
                                      (uint2*)shi, (uint2*)slo, n4);

    tgemm<0, 0><<<dim3(2, mby), 256, SMEM_TOT>>>(qhi, qlo, offh, offl, b_off, offb, nullptr, nullptr, M, 256, 256);
    tgemm<0, 0><<<dim3(1, mby), 256, SMEM_TOT>>>(qhi, qlo, atth, attl, b_attn, attn, nullptr, nullptr, M, 256, 128);
    tgemm<0, 0><<<dim3(2, mby), 256, SMEM_TOT>>>(shi, slo, valh, vall, b_val, val, nullptr, nullptr, M, 256, 256);

    msda_prep<<<(M * 8 + 255) / 256, 256>>>(refp, offb, attn, sidx, sw);
    msda_gather<<<M, 256>>>(sidx, sw, val, aohi, aolo);

    tgemm<0, 0><<<dim3(2, mby), 256, SMEM_TOT>>>(aohi, aolo, outh, outl, b_out, src2, nullptr, nullptr, M, 256, 256);
    add_ln<1><<<M, 256>>>(src, src2, g1p, be1p, x, xhi, xlo);

    tgemm<1, 1><<<dim3(8, mby), 256, SMEM_TOT>>>(xhi, xlo, w1h, w1l, b1, nullptr, h1hi, h1lo, M, 256, 1024);
    tgemm<0, 0><<<dim3(2, mby), 256, SMEM_TOT>>>(h1hi, h1lo, w2h, w2l, b2, ff, nullptr, nullptr, M, 1024, 256);
    add_ln<0><<<M, 256>>>(x, ff, g2p, be2p, out, nullptr, nullptr);
}

// round 11
// speedup vs baseline: 2.3316x; 1.2014x over previous
#include <cuda_runtime.h>
#include <cuda_fp16.h>
#include <math.h>
#include <cstdint>

#define S_TOTAL 13294
#define BATCHN 2
#define MTOT (BATCHN * S_TOTAL)   // 26588
#define DM 256
#define DF 1024

// ---------------- scratch (static device globals; no runtime allocation) -------------
__device__ __half g_qh[MTOT * DM];     // (src+pos) fp16
__device__ __half g_sh[MTOT * DM];     // src fp16
__device__ float g_offb[MTOT * DM];
__device__ float g_attn[MTOT * 128];
__device__ float g_val[MTOT * DM];
__device__ __half g_aoh[MTOT * DM];    // attention output fp16
__device__ float g_src2[MTOT * DM];
__device__ float g_x[MTOT * DM];
__device__ __half g_xh[MTOT * DM];
__device__ __half g_h1h[MTOT * DF];
__device__ float g_ff[MTOT * DM];

// msda precomputed gather tables
__device__ int4   g_sidx[MTOT * 8 * 16];
__device__ float4 g_sw[MTOT * 8 * 16];

// transposed + fp16-split weights: [N][K] layout
// qproj(off|attn) 384x256 @0; val @98304; out @163840; W1 @229376; W2 @491520
#define WT_TOTAL 753664
__device__ __half g_wt_hi[WT_TOTAL];
__device__ __half g_wt_lo[WT_TOTAL];
__device__ float g_bqa[384];

// ---------------- helpers -------------------------------------------------------------
__device__ __forceinline__ uint32_t smem_u32(const void* p) {
    uint32_t a;
    asm("{ .reg .u64 t; cvta.to.shared.u64 t, %1; cvt.u32.u64 %0, t; }" : "=r"(a) : "l"(p));
    return a;
}
__device__ __forceinline__ void ldsm_x4(uint32_t (&r)[4], uint32_t addr) {
    asm volatile("ldmatrix.sync.aligned.m8n8.x4.shared.b16 {%0,%1,%2,%3}, [%4];"
                 : "=r"(r[0]), "=r"(r[1]), "=r"(r[2]), "=r"(r[3]) : "r"(addr));
}
__device__ __forceinline__ void mma_f16(float (&c)[4], const uint32_t (&a)[4],
                                        uint32_t b0, uint32_t b1) {
    asm volatile("mma.sync.aligned.m16n8k16.row.col.f32.f16.f16.f32 "
                 "{%0,%1,%2,%3}, {%4,%5,%6,%7}, {%8,%9}, {%0,%1,%2,%3};"
                 : "+f"(c[0]), "+f"(c[1]), "+f"(c[2]), "+f"(c[3])
                 : "r"(a[0]), "r"(a[1]), "r"(a[2]), "r"(a[3]), "r"(b0), "r"(b1));
}
__device__ __forceinline__ void splith(float v, __half& h, __half& l) {
    h = __float2half_rn(v);
    l = __float2half_rn(v - __half2float(h));
}
__device__ __forceinline__ uint32_t packh(__half a, __half b) {
    return (uint32_t)__half_as_ushort(a) | ((uint32_t)__half_as_ushort(b) << 16);
}
__device__ __forceinline__ void cp16(uint32_t dst, const void* src, bool pred) {
    int sz = pred ? 16 : 0;
    asm volatile("cp.async.cg.shared.global [%0], [%1], 16, %2;"
                 :: "r"(dst), "l"(src), "r"(sz) : "memory");
}
#define CP_COMMIT() asm volatile("cp.async.commit_group;" ::: "memory")
#define CP_WAIT(n)  asm volatile("cp.async.wait_group %0;" :: "n"(n) : "memory")

// ---------------- all weights: transpose + fp16 split + merged bias -------------------
__global__ void convw_all(const float* __restrict__ W_off, const float* __restrict__ W_attn,
                          const float* __restrict__ W_val, const float* __restrict__ W_out,
                          const float* __restrict__ W1, const float* __restrict__ W2,
                          const float* __restrict__ b_off, const float* __restrict__ b_attn,
                          __half* __restrict__ hi, __half* __restrict__ lo,
                          float* __restrict__ bqa) {
    int i = blockIdx.x * blockDim.x + threadIdx.x;
    if (i < 384) bqa[i] = (i < 256) ? b_off[i] : b_attn[i - 256];
    if (i >= WT_TOTAL) return;
    float x;
    if (i < 98304) {               // qproj merged: N=384, K=256
        int n = i >> 8, k = i & 255;
        x = (n < 256) ? W_off[(size_t)k * 256 + n] : W_attn[(size_t)k * 128 + (n - 256)];
    } else if (i < 163840) {       // val
        int li = i - 98304; int n = li >> 8, k = li & 255;
        x = W_val[(size_t)k * 256 + n];
    } else if (i < 229376) {       // out
        int li = i - 163840; int n = li >> 8, k = li & 255;
        x = W_out[(size_t)k * 256 + n];
    } else if (i < 491520) {       // W1: N=1024, K=256
        int li = i - 229376; int n = li >> 8, k = li & 255;
        x = W1[(size_t)k * 1024 + n];
    } else {                       // W2: N=256, K=1024
        int li = i - 491520; int n = li >> 10, k = li & 1023;
        x = W2[(size_t)k * 256 + n];
    }
    splith(x, hi[i], lo[i]);
}

// ---------------- activation convert: q = src+pos -> fp16, src -> fp16 ----------------
__global__ void qsplit(const float* __restrict__ src, const float* __restrict__ pos,
                       uint2* __restrict__ qh, uint2* __restrict__ sh, int n4) {
    int i = blockIdx.x * blockDim.x + threadIdx.x;
    if (i >= n4) return;
    float4 s = ((const float4*)src)[i];
    float4 p = ((const float4*)pos)[i];
    qh[i] = make_uint2(packh(__float2half_rn(s.x + p.x), __float2half_rn(s.y + p.y)),
                       packh(__float2half_rn(s.z + p.z), __float2half_rn(s.w + p.w)));
    sh[i] = make_uint2(packh(__float2half_rn(s.x), __float2half_rn(s.y)),
                       packh(__float2half_rn(s.z), __float2half_rn(s.w)));
}

// ---------------- fp16 tensor-core GEMM (mma.sync m16n8k16, A single + W hi/lo) -------
// C[M,N] = A @ Wt^T + bias. CTA 128x128, BK=32, 8 warps (2x4), warp tile 64x32.
// cp.async 2-stage double buffer. Dual fp32 output routing (col<N1 -> Cf, else C2f).
#define SA 40
#define BUF_B   10240           // 128 * SA * 2 bytes
#define STAGE_B 30720           // A + Bhi + Blo
#define SMEM_TOT (2 * STAGE_B)  // 61440

template <int RELU, int SPLITOUT>
__global__ void __launch_bounds__(256, 2)
tgemm(const __half* __restrict__ A,
      const __half* __restrict__ Bhi, const __half* __restrict__ Blo,
      const float* __restrict__ bias, float* __restrict__ Cf, float* __restrict__ C2f,
      __half* __restrict__ Ch, int M, int K, int N, int N1) {
    extern __shared__ char dsm[];
    const uint32_t sb = smem_u32(dsm);

    const int t = threadIdx.x;
    const int w = t >> 5;
    const int lane = t & 31;
    const int row0 = blockIdx.y * 128;
    const int col0 = blockIdx.x * 128;
    const int wr = (w >> 2) * 64;
    const int wc = (w & 3) * 32;
    const int N2 = N - N1;

    const uint32_t aOff = (uint32_t)(wr * (SA * 2)) + (lane & 15) * (SA * 2) + ((lane >> 4) << 4);
    const uint32_t bOff = (uint32_t)(wc * (SA * 2)) + ((lane & 7) + ((lane >> 4) << 3)) * (SA * 2)
                        + (((lane >> 3) & 1) << 4);

    float acc[4][4][4];
#pragma unroll
    for (int i = 0; i < 4; i++)
#pragma unroll
        for (int j = 0; j < 4; j++)
#pragma unroll
            for (int r = 0; r < 4; r++) acc[i][j][r] = 0.f;

    const int nk = K >> 5;

    auto load_chunk = [&](int ch) {
        const int k0 = ch << 5;
        const uint32_t st = sb + (uint32_t)(ch & 1) * STAGE_B;
        // A: 128x32 fp16 = 512 uint4, 2 per thread
#pragma unroll
        for (int half = 0; half < 2; half++) {
            int q = t + half * 256;
            int r = q >> 2;
            int c8 = (q & 3) << 3;
            uint32_t doff = (uint32_t)(r * (SA * 2) + c8 * 2);
            bool okA = (row0 + r) < M;
            size_t sA = (size_t)(row0 + r) * K + k0 + c8;
            cp16(st + doff, &A[okA ? sA : 0], okA);
            size_t sB = (size_t)(col0 + r) * K + k0 + c8;
            cp16(st + BUF_B + doff, &Bhi[sB], true);
            cp16(st + 2 * BUF_B + doff, &Blo[sB], true);
        }
        CP_COMMIT();
    };

    load_chunk(0);
    for (int ch = 0; ch < nk; ++ch) {
        if (ch + 1 < nk) {
            load_chunk(ch + 1);
            CP_WAIT(1);
        } else {
            CP_WAIT(0);
        }
        __syncthreads();

        const uint32_t st = sb + (uint32_t)(ch & 1) * STAGE_B;
        const uint32_t uA = st, uBhi = st + BUF_B, uBlo = st + 2 * BUF_B;
#pragma unroll
        for (int k16 = 0; k16 < 2; k16++) {
            const uint32_t kb = (uint32_t)(k16 << 5);
            uint32_t aF[4][4];
#pragma unroll
            for (int i = 0; i < 4; i++)
                ldsm_x4(aF[i], uA + aOff + i * (16 * SA * 2) + kb);
#pragma unroll
            for (int jp = 0; jp < 2; jp++) {
                uint32_t bH[4], bL[4];
                ldsm_x4(bH, uBhi + bOff + jp * (16 * SA * 2) + kb);
                ldsm_x4(bL, uBlo + bOff + jp * (16 * SA * 2) + kb);
#pragma unroll
                for (int i = 0; i < 4; i++) {
                    mma_f16(acc[i][jp * 2 + 0], aF[i], bH[0], bH[1]);
                    mma_f16(acc[i][jp * 2 + 0], aF[i], bL[0], bL[1]);
                    mma_f16(acc[i][jp * 2 + 1], aF[i], bH[2], bH[3]);
                    mma_f16(acc[i][jp * 2 + 1], aF[i], bL[2], bL[3]);
                }
            }
        }
        __syncthreads();
    }

    // ---- epilogue
#pragma unroll
    for (int i = 0; i < 4; i++) {
#pragma unroll
        for (int j = 0; j < 4; j++) {
            int col = col0 + wc + j * 8 + (lane & 3) * 2;
            float bx = bias[col], by = bias[col + 1];
            int rowA = row0 + wr + i * 16 + (lane >> 2);
            int rowB = rowA + 8;
            float v0 = acc[i][j][0] + bx, v1 = acc[i][j][1] + by;
            float v2 = acc[i][j][2] + bx, v3 = acc[i][j][3] + by;
            if (RELU) {
                v0 = fmaxf(v0, 0.f); v1 = fmaxf(v1, 0.f);
                v2 = fmaxf(v2, 0.f); v3 = fmaxf(v3, 0.f);
            }
            if (SPLITOUT) {
                if (rowA < M)
                    *(uint32_t*)&Ch[(size_t)rowA * N + col] = packh(__float2half_rn(v0), __float2half_rn(v1));
                if (rowB < M)
                    *(uint32_t*)&Ch[(size_t)rowB * N + col] = packh(__float2half_rn(v2), __float2half_rn(v3));
            } else if (col < N1) {
                if (rowA < M) *(float2*)&Cf[(size_t)rowA * N1 + col] = make_float2(v0, v1);
                if (rowB < M) *(float2*)&Cf[(size_t)rowB * N1 + col] = make_float2(v2, v3);
            } else {
                int c2 = col - N1;
                if (rowA < M) *(float2*)&C2f[(size_t)rowA * N2 + c2] = make_float2(v0, v1);
                if (rowB < M) *(float2*)&C2f[(size_t)rowB * N2 + c2] = make_float2(v2, v3);
            }
        }
    }
}

// ---------------- msda prep: one thread per (row, head) -------------------------------
__global__ void __launch_bounds__(256) msda_prep(
    const float* __restrict__ refp, const float* __restrict__ off,
    const float* __restrict__ attnlog, int4* __restrict__ sidx, float4* __restrict__ sw) {
    int tid = blockIdx.x * blockDim.x + threadIdx.x;
    if (tid >= MTOT * 8) return;
    int row = tid >> 3, h = tid & 7;
    int n = (row >= S_TOTAL) ? 1 : 0;

    float l[16];
    const float4* al4 = (const float4*)(attnlog + (size_t)row * 128 + h * 16);
#pragma unroll
    for (int j = 0; j < 4; j++) {
        float4 v = al4[j];
        l[j * 4 + 0] = v.x; l[j * 4 + 1] = v.y; l[j * 4 + 2] = v.z; l[j * 4 + 3] = v.w;
    }
    float m = -1e30f;
#pragma unroll
    for (int j = 0; j < 16; j++) m = fmaxf(m, l[j]);
    float den = 0.f;
#pragma unroll
    for (int j = 0; j < 16; j++) { l[j] = __expf(l[j] - m); den += l[j]; }
    float inv = 1.f / den;

    const float2* offp = (const float2*)(off + (size_t)row * 256 + h * 32);
    const float* rp = refp + (size_t)row * 8;

    const int Hs[4]     = {100, 50, 25, 13};
    const int starts[4] = {0, 10000, 12500, 13125};

#pragma unroll
    for (int lv = 0; lv < 4; lv++) {
        int H = Hs[lv], W = H;
        float rx = rp[lv * 2 + 0];
        float ry = rp[lv * 2 + 1];
        int base = n * S_TOTAL + starts[lv];
#pragma unroll
        for (int p = 0; p < 4; p++) {
            float2 o = offp[lv * 4 + p];
            float x = (rx + o.x / (float)W) * (float)W - 0.5f;
            float y = (ry + o.y / (float)H) * (float)H - 0.5f;
            float x0f = floorf(x), y0f = floorf(y);
            int x0 = (int)x0f, y0 = (int)y0f;
            int x1 = x0 + 1, y1 = y0 + 1;
            float wx1 = x - x0f, wx0 = 1.f - wx1;
            float wy1 = y - y0f, wy0 = 1.f - wy1;
            float aw = l[lv * 4 + p] * inv;

            float fx0 = ((unsigned)x0 < (unsigned)W) ? 1.f : 0.f;
            float fx1 = ((unsigned)x1 < (unsigned)W) ? 1.f : 0.f;
            float fy0 = ((unsigned)y0 < (unsigned)H) ? 1.f : 0.f;
            float fy1 = ((unsigned)y1 < (unsigned)H) ? 1.f : 0.f;
            int xc0 = min(max(x0, 0), W - 1);
            int xc1 = min(max(x1, 0), W - 1);
            int yc0 = min(max(y0, 0), H - 1);
            int yc1 = min(max(y1, 0), H - 1);

            int4 idx;
            idx.x = base + yc0 * W + xc0;
            idx.y = base + yc0 * W + xc1;
            idx.z = base + yc1 * W + xc0;
            idx.w = base + yc1 * W + xc1;
            float4 wv;
            wv.x = aw * wy0 * wx0 * fy0 * fx0;
            wv.y = aw * wy0 * wx1 * fy0 * fx1;
            wv.z = aw * wy1 * wx0 * fy1 * fx0;
            wv.w = aw * wy1 * wx1 * fy1 * fx1;
            sidx[(size_t)tid * 16 + lv * 4 + p] = idx;
            sw[(size_t)tid * 16 + lv * 4 + p] = wv;
        }
    }
}

// ---------------- msda gather: block = token row, warp = head, lane = channel ---------
__global__ void __launch_bounds__(256) msda_gather(
    const int4* __restrict__ sidx, const float4* __restrict__ sw,
    const float* __restrict__ value, __half* __restrict__ outh) {
    int row = blockIdx.x;
    int h = threadIdx.x >> 5;
    int lane = threadIdx.x & 31;
    const int4* ip = sidx + ((size_t)row * 8 + h) * 16;
    const float4* wp = sw + ((size_t)row * 8 + h) * 16;
    const float* vp = value + h * 32 + lane;

    float acc = 0.f;
#pragma unroll
    for (int p = 0; p < 16; p++) {
        int4 id = ip[p];
        float4 wv = wp[p];
        acc = fmaf(wv.x, vp[(size_t)id.x << 8], acc);
        acc = fmaf(wv.y, vp[(size_t)id.y << 8], acc);
        acc = fmaf(wv.z, vp[(size_t)id.z << 8], acc);
        acc = fmaf(wv.w, vp[(size_t)id.w << 8], acc);
    }
    outh[(size_t)row * 256 + h * 32 + lane] = __float2half_rn(acc);
}

// ---------------- fused residual add + LayerNorm (C=256), optional fp16 out -----------
template <int SPLIT>
__global__ void __launch_bounds__(256) add_ln(const float* __restrict__ a,
                                              const float* __restrict__ b,
                                              const float* __restrict__ g,
                                              const float* __restrict__ be,
                                              float* __restrict__ out,
                                              __half* __restrict__ oh) {
    int row = blockIdx.x;
    int t = threadIdx.x;
    float v = a[(size_t)row * 256 + t] + b[(size_t)row * 256 + t];

    __shared__ float red[8];
    __shared__ float stat[2];

    float s = v;
#pragma unroll
    for (int o = 16; o; o >>= 1) s += __shfl_xor_sync(0xffffffffu, s, o);
    if ((t & 31) == 0) red[t >> 5] = s;
    __syncthreads();
    if (t == 0) {
        float tot = 0.f;
        for (int i = 0; i < 8; i++) tot += red[i];
        stat[0] = tot * (1.f / 256.f);
    }
    __syncthreads();
    float mean = stat[0];
    float d = v - mean;

    s = d * d;
#pragma unroll
    for (int o = 16; o; o >>= 1) s += __shfl_xor_sync(0xffffffffu, s, o);
    __syncthreads();
    if ((t & 31) == 0) red[t >> 5] = s;
    __syncthreads();
    if (t == 0) {
        float tot = 0.f;
        for (int i = 0; i < 8; i++) tot += red[i];
        stat[1] = tot * (1.f / 256.f);
    }
    __syncthreads();
    float var = stat[1];

    float y = d * rsqrtf(var + 1e-5f) * g[t] + be[t];
    out[(size_t)row * 256 + t] = y;
    if (SPLIT) oh[(size_t)row * 256 + t] = __float2half_rn(y);
}

// ---------------- launch -------------------------------------------------------------
extern "C" void kernel_launch(void* const* d_in, const int* in_sizes, int n_in,
                              void* d_out, int out_size) {
    const float* src   = (const float*)d_in[0];
    const float* pos   = (const float*)d_in[1];
    const float* refp  = (const float*)d_in[2];
    const float* W_off  = (const float*)d_in[5];
    const float* b_off  = (const float*)d_in[6];
    const float* W_attn = (const float*)d_in[7];
    const float* b_attn = (const float*)d_in[8];
    const float* W_val  = (const float*)d_in[9];
    const float* b_val  = (const float*)d_in[10];
    const float* W_out  = (const float*)d_in[11];
    const float* b_out  = (const float*)d_in[12];
    const float* W1     = (const float*)d_in[13];
    const float* b1     = (const float*)d_in[14];
    const float* W2     = (const float*)d_in[15];
    const float* b2     = (const float*)d_in[16];
    const float* g1p    = (const float*)d_in[17];
    const float* be1p   = (const float*)d_in[18];
    const float* g2p    = (const float*)d_in[19];
    const float* be2p   = (const float*)d_in[20];
    float* out = (float*)d_out;

    __half *qh, *sh, *aoh, *xh, *h1h;
    float *offb, *attn, *val, *src2, *x, *ff, *bqa;
    int4* sidx;
    float4* sw;
    cudaGetSymbolAddress((void**)&qh, g_qh);     cudaGetSymbolAddress((void**)&sh, g_sh);
    cudaGetSymbolAddress((void**)&offb, g_offb); cudaGetSymbolAddress((void**)&attn, g_attn);
    cudaGetSymbolAddress((void**)&val, g_val);   cudaGetSymbolAddress((void**)&aoh, g_aoh);
    cudaGetSymbolAddress((void**)&src2, g_src2); cudaGetSymbolAddress((void**)&x, g_x);
    cudaGetSymbolAddress((void**)&xh, g_xh);     cudaGetSymbolAddress((void**)&h1h, g_h1h);
    cudaGetSymbolAddress((void**)&ff, g_ff);     cudaGetSymbolAddress((void**)&bqa, g_bqa);
    cudaGetSymbolAddress((void**)&sidx, g_sidx); cudaGetSymbolAddress((void**)&sw, g_sw);

    __half *wh, *wl;
    cudaGetSymbolAddress((void**)&wh, g_wt_hi);
    cudaGetSymbolAddress((void**)&wl, g_wt_lo);
    __half *qph = wh + 0,      *qpl = wl + 0;        // merged off|attn, N=384
    __half *valh = wh + 98304, *vall = wl + 98304;
    __half *outh = wh + 163840, *outl = wl + 163840;
    __half *w1h  = wh + 229376, *w1l  = wl + 229376;
    __half *w2h  = wh + 491520, *w2l  = wl + 491520;

    cudaFuncSetAttribute(tgemm<0, 0>, cudaFuncAttributeMaxDynamicSharedMemorySize, SMEM_TOT);
    cudaFuncSetAttribute(tgemm<1, 1>, cudaFuncAttributeMaxDynamicSharedMemorySize, SMEM_TOT);

    const int M = MTOT;
    const int mby = (M + 127) / 128;   // 208
    const int n4 = M * DM / 4;

    convw_all<<<(WT_TOTAL + 255) / 256, 256>>>(W_off, W_attn, W_val, W_out, W1, W2,
                                               b_off, b_attn, wh, wl, bqa);
    qsplit<<<(n4 + 255) / 256, 256>>>(src, pos, (uint2*)qh, (uint2*)sh, n4);

    // merged qproj: cols 0..255 -> offb, 256..383 -> attn
    tgemm<0, 0><<<dim3(3, mby), 256, SMEM_TOT>>>(qh, qph, qpl, bqa, offb, attn, nullptr, M, 256, 384, 256);
    tgemm<0, 0><<<dim3(2, mby), 256, SMEM_TOT>>>(sh, valh, vall, b_val, val, nullptr, nullptr, M, 256, 256, 256);

    msda_prep<<<(M * 8 + 255) / 256, 256>>>(refp, offb, attn, sidx, sw);
    msda_gather<<<M, 256>>>(sidx, sw, val, aoh);

    tgemm<0, 0><<<dim3(2, mby), 256, SMEM_TOT>>>(aoh, outh, outl, b_out, src2, nullptr, nullptr, M, 256, 256, 256);
    add_ln<1><<<M, 256>>>(src, src2, g1p, be1p, x, xh);

    tgemm<1, 1><<<dim3(8, mby), 256, SMEM_TOT>>>(xh, w1h, w1l, b1, nullptr, nullptr, h1h, M, 256, 1024, 1024);
    tgemm<0, 0><<<dim3(2, mby), 256, SMEM_TOT>>>(h1h, w2h, w2l, b2, ff, nullptr, nullptr, M, 1024, 256, 256);
    add_ln<0><<<M, 256>>>(x, ff, g2p, be2p, out, nullptr);
}

// round 15
// speedup vs baseline: 2.9200x; 1.2523x over previous
#include <cuda_runtime.h>
#include <cuda_fp16.h>
#include <math.h>
#include <cstdint>

#define S_TOTAL 13294
#define BATCHN 2
#define MTOT (BATCHN * S_TOTAL)   // 26588
#define DM 256
#define DF 1024

// ---------------- scratch (static device globals; no runtime allocation) -------------
__device__ __half g_qh[MTOT * DM];     // (src+pos) fp16
__device__ __half g_sh[MTOT * DM];     // src fp16
__device__ float g_offb[MTOT * DM];
__device__ float g_attn[MTOT * 128];
__device__ __half g_valh[MTOT * DM];   // value fp16
__device__ __half g_aoh[MTOT * DM];    // attention output fp16
__device__ float g_src2[MTOT * DM];
__device__ float g_x[MTOT * DM];
__device__ __half g_xh[MTOT * DM];
__device__ __half g_h1h[MTOT * DF];
__device__ float g_ff[MTOT * DM];

// transposed + fp16-split weights: [N][K] layout
// qproj(off|attn) 384x256 @0; val @98304; out @163840; W1 @229376; W2 @491520
#define WT_TOTAL 753664
__device__ __half g_wt_hi[WT_TOTAL];
__device__ __half g_wt_lo[WT_TOTAL];
__device__ float g_bqa[384];

// ---------------- helpers -------------------------------------------------------------
__device__ __forceinline__ uint32_t smem_u32(const void* p) {
    uint32_t a;
    asm("{ .reg .u64 t; cvta.to.shared.u64 t, %1; cvt.u32.u64 %0, t; }" : "=r"(a) : "l"(p));
    return a;
}
__device__ __forceinline__ void ldsm_x4(uint32_t (&r)[4], uint32_t addr) {
    asm volatile("ldmatrix.sync.aligned.m8n8.x4.shared.b16 {%0,%1,%2,%3}, [%4];"
                 : "=r"(r[0]), "=r"(r[1]), "=r"(r[2]), "=r"(r[3]) : "r"(addr));
}
__device__ __forceinline__ void mma_f16(float (&c)[4], const uint32_t (&a)[4],
                                        uint32_t b0, uint32_t b1) {
    asm volatile("mma.sync.aligned.m16n8k16.row.col.f32.f16.f16.f32 "
                 "{%0,%1,%2,%3}, {%4,%5,%6,%7}, {%8,%9}, {%0,%1,%2,%3};"
                 : "+f"(c[0]), "+f"(c[1]), "+f"(c[2]), "+f"(c[3])
                 : "r"(a[0]), "r"(a[1]), "r"(a[2]), "r"(a[3]), "r"(b0), "r"(b1));
}
__device__ __forceinline__ void splith(float v, __half& h, __half& l) {
    h = __float2half_rn(v);
    l = __float2half_rn(v - __half2float(h));
}
__device__ __forceinline__ uint32_t packh(__half a, __half b) {
    return (uint32_t)__half_as_ushort(a) | ((uint32_t)__half_as_ushort(b) << 16);
}
__device__ __forceinline__ void cp16(uint32_t dst, const void* src, bool pred) {
    int sz = pred ? 16 : 0;
    asm volatile("cp.async.cg.shared.global [%0], [%1], 16, %2;"
                 :: "r"(dst), "l"(src), "r"(sz) : "memory");
}
#define CP_COMMIT() asm volatile("cp.async.commit_group;" ::: "memory")
#define CP_WAIT(n)  asm volatile("cp.async.wait_group %0;" :: "n"(n) : "memory")

// ---------------- all weights: transpose + fp16 split + merged bias -------------------
__global__ void convw_all(const float* __restrict__ W_off, const float* __restrict__ W_attn,
                          const float* __restrict__ W_val, const float* __restrict__ W_out,
                          const float* __restrict__ W1, const float* __restrict__ W2,
                          const float* __restrict__ b_off, const float* __restrict__ b_attn,
                          __half* __restrict__ hi, __half* __restrict__ lo,
                          float* __restrict__ bqa) {
    int i = blockIdx.x * blockDim.x + threadIdx.x;
    if (i < 384) bqa[i] = (i < 256) ? b_off[i] : b_attn[i - 256];
    if (i >= WT_TOTAL) return;
    float x;
    if (i < 98304) {               // qproj merged: N=384, K=256
        int n = i >> 8, k = i & 255;
        x = (n < 256) ? W_off[(size_t)k * 256 + n] : W_attn[(size_t)k * 128 + (n - 256)];
    } else if (i < 163840) {       // val
        int li = i - 98304; int n = li >> 8, k = li & 255;
        x = W_val[(size_t)k * 256 + n];
    } else if (i < 229376) {       // out
        int li = i - 163840; int n = li >> 8, k = li & 255;
        x = W_out[(size_t)k * 256 + n];
    } else if (i < 491520) {       // W1: N=1024, K=256
        int li = i - 229376; int n = li >> 8, k = li & 255;
        x = W1[(size_t)k * 1024 + n];
    } else {                       // W2: N=256, K=1024
        int li = i - 491520; int n = li >> 10, k = li & 1023;
        x = W2[(size_t)k * 256 + n];
    }
    splith(x, hi[i], lo[i]);
}

// ---------------- activation convert: q = src+pos -> fp16, src -> fp16 ----------------
__global__ void qsplit(const float* __restrict__ src, const float* __restrict__ pos,
                       uint2* __restrict__ qh, uint2* __restrict__ sh, int n4) {
    int i = blockIdx.x * blockDim.x + threadIdx.x;
    if (i >= n4) return;
    float4 s = ((const float4*)src)[i];
    float4 p = ((const float4*)pos)[i];
    qh[i] = make_uint2(packh(__float2half_rn(s.x + p.x), __float2half_rn(s.y + p.y)),
                       packh(__float2half_rn(s.z + p.z), __float2half_rn(s.w + p.w)));
    sh[i] = make_uint2(packh(__float2half_rn(s.x), __float2half_rn(s.y)),
                       packh(__float2half_rn(s.z), __float2half_rn(s.w)));
}

// ---------------- fp16 tensor-core GEMM (mma.sync m16n8k16, A single + W hi/lo) -------
// CTA 128x128, BK=32, 8 warps (2x4), warp tile 64x32. cp.async 3-stage pipeline.
// Output routing: SPLITOUT -> fp16 Ch; else fp32, col<N1 -> Cf, else C2f.
#define SA 40
#define BUF_B   10240           // 128 * SA * 2 bytes
#define STAGE_B 30720           // A + Bhi + Blo
#define NSTAGE 3
#define SMEM_TOT (NSTAGE * STAGE_B)   // 92160

template <int RELU, int SPLITOUT>
__global__ void __launch_bounds__(256, 2)
tgemm(const __half* __restrict__ A,
      const __half* __restrict__ Bhi, const __half* __restrict__ Blo,
      const float* __restrict__ bias, float* __restrict__ Cf, float* __restrict__ C2f,
      __half* __restrict__ Ch, int M, int K, int N, int N1) {
    extern __shared__ char dsm[];
    const uint32_t sb = smem_u32(dsm);

    const int t = threadIdx.x;
    const int w = t >> 5;
    const int lane = t & 31;
    const int row0 = blockIdx.y * 128;
    const int col0 = blockIdx.x * 128;
    const int wr = (w >> 2) * 64;
    const int wc = (w & 3) * 32;
    const int N2 = N - N1;

    const uint32_t aOff = (uint32_t)(wr * (SA * 2)) + (lane & 15) * (SA * 2) + ((lane >> 4) << 4);
    const uint32_t bOff = (uint32_t)(wc * (SA * 2)) + ((lane & 7) + ((lane >> 4) << 3)) * (SA * 2)
                        + (((lane >> 3) & 1) << 4);

    float acc[4][4][4];
#pragma unroll
    for (int i = 0; i < 4; i++)
#pragma unroll
        for (int j = 0; j < 4; j++)
#pragma unroll
            for (int r = 0; r < 4; r++) acc[i][j][r] = 0.f;

    const int nk = K >> 5;

    auto load_chunk = [&](int ch) {
        const int k0 = ch << 5;
        const uint32_t st = sb + (uint32_t)(ch % NSTAGE) * STAGE_B;
#pragma unroll
        for (int half = 0; half < 2; half++) {
            int q = t + half * 256;
            int r = q >> 2;
            int c8 = (q & 3) << 3;
            uint32_t doff = (uint32_t)(r * (SA * 2) + c8 * 2);
            bool okA = (row0 + r) < M;
            size_t sA = (size_t)(row0 + r) * K + k0 + c8;
            cp16(st + doff, &A[okA ? sA : 0], okA);
            size_t sB = (size_t)(col0 + r) * K + k0 + c8;
            cp16(st + BUF_B + doff, &Bhi[sB], true);
            cp16(st + 2 * BUF_B + doff, &Blo[sB], true);
        }
        CP_COMMIT();
    };

    load_chunk(0);
    if (nk > 1) load_chunk(1);
    for (int ch = 0; ch < nk; ++ch) {
        if (ch + 2 < nk) {
            load_chunk(ch + 2);
            CP_WAIT(2);
        } else if (ch + 1 < nk) {
            CP_WAIT(1);
        } else {
            CP_WAIT(0);
        }
        __syncthreads();

        const uint32_t st = sb + (uint32_t)(ch % NSTAGE) * STAGE_B;
        const uint32_t uA = st, uBhi = st + BUF_B, uBlo = st + 2 * BUF_B;
#pragma unroll
        for (int k16 = 0; k16 < 2; k16++) {
            const uint32_t kb = (uint32_t)(k16 << 5);
            uint32_t aF[4][4];
#pragma unroll
            for (int i = 0; i < 4; i++)
                ldsm_x4(aF[i], uA + aOff + i * (16 * SA * 2) + kb);
#pragma unroll
            for (int jp = 0; jp < 2; jp++) {
                uint32_t bH[4], bL[4];
                ldsm_x4(bH, uBhi + bOff + jp * (16 * SA * 2) + kb);
                ldsm_x4(bL, uBlo + bOff + jp * (16 * SA * 2) + kb);
#pragma unroll
                for (int i = 0; i < 4; i++) {
                    mma_f16(acc[i][jp * 2 + 0], aF[i], bH[0], bH[1]);
                    mma_f16(acc[i][jp * 2 + 0], aF[i], bL[0], bL[1]);
                    mma_f16(acc[i][jp * 2 + 1], aF[i], bH[2], bH[3]);
                    mma_f16(acc[i][jp * 2 + 1], aF[i], bL[2], bL[3]);
                }
            }
        }
        __syncthreads();
    }

    // ---- epilogue
#pragma unroll
    for (int i = 0; i < 4; i++) {
#pragma unroll
        for (int j = 0; j < 4; j++) {
            int col = col0 + wc + j * 8 + (lane & 3) * 2;
            float bx = bias[col], by = bias[col + 1];
            int rowA = row0 + wr + i * 16 + (lane >> 2);
            int rowB = rowA + 8;
            float v0 = acc[i][j][0] + bx, v1 = acc[i][j][1] + by;
            float v2 = acc[i][j][2] + bx, v3 = acc[i][j][3] + by;
            if (RELU) {
                v0 = fmaxf(v0, 0.f); v1 = fmaxf(v1, 0.f);
                v2 = fmaxf(v2, 0.f); v3 = fmaxf(v3, 0.f);
            }
            if (SPLITOUT) {
                if (rowA < M)
                    *(uint32_t*)&Ch[(size_t)rowA * N + col] = packh(__float2half_rn(v0), __float2half_rn(v1));
                if (rowB < M)
                    *(uint32_t*)&Ch[(size_t)rowB * N + col] = packh(__float2half_rn(v2), __float2half_rn(v3));
            } else if (col < N1) {
                if (rowA < M) *(float2*)&Cf[(size_t)rowA * N1 + col] = make_float2(v0, v1);
                if (rowB < M) *(float2*)&Cf[(size_t)rowB * N1 + col] = make_float2(v2, v3);
            } else {
                int c2 = col - N1;
                if (rowA < M) *(float2*)&C2f[(size_t)rowA * N2 + c2] = make_float2(v0, v1);
                if (rowB < M) *(float2*)&C2f[(size_t)rowB * N2 + c2] = make_float2(v2, v3);
            }
        }
    }
}

// ---------------- fused msda: prep in smem + gather -----------------------------------
// Block = token row. Phase 1: threads 0..127 each own one (head, point): softmax via
// shfl over 16-lane groups, coords -> smem tables. Phase 2: warp h gathers, lane = chan.
__global__ void __launch_bounds__(256) msda_fused(
    const float* __restrict__ refp, const float* __restrict__ off,
    const float* __restrict__ attnlog, const __half* __restrict__ valh,
    __half* __restrict__ outh) {
    __shared__ int4   sidx[128];
    __shared__ float4 sw[128];

    const int row = blockIdx.x;
    const int t = threadIdx.x;
    const int n = (row >= S_TOTAL) ? 1 : 0;

    if (t < 128) {
        const int h = t >> 4;       // head
        const int p = t & 15;       // point (lv*4 + pp)
        const int lv = p >> 2;

        float lg = attnlog[(size_t)row * 128 + h * 16 + p];
        float m = lg;
#pragma unroll
        for (int msk = 8; msk; msk >>= 1)
            m = fmaxf(m, __shfl_xor_sync(0xffffffffu, m, msk, 16));
        float e = __expf(lg - m);
        float den = e;
#pragma unroll
        for (int msk = 8; msk; msk >>= 1)
            den += __shfl_xor_sync(0xffffffffu, den, msk, 16);
        float aw = e / den;

        const int H = (lv == 0) ? 100 : (lv == 1) ? 50 : (lv == 2) ? 25 : 13;
        const int W = H;
        const int start = (lv == 0) ? 0 : (lv == 1) ? 10000 : (lv == 2) ? 12500 : 13125;
        const int base = n * S_TOTAL + start;

        float2 o = ((const float2*)(off + (size_t)row * 256 + h * 32))[p];
        float rx = refp[(size_t)row * 8 + lv * 2 + 0];
        float ry = refp[(size_t)row * 8 + lv * 2 + 1];

        float x = (rx + o.x / (float)W) * (float)W - 0.5f;
        float y = (ry + o.y / (float)H) * (float)H - 0.5f;
        float x0f = floorf(x), y0f = floorf(y);
        int x0 = (int)x0f, y0 = (int)y0f;
        int x1 = x0 + 1, y1 = y0 + 1;
        float wx1 = x - x0f, wx0 = 1.f - wx1;
        float wy1 = y - y0f, wy0 = 1.f - wy1;

        float fx0 = ((unsigned)x0 < (unsigned)W) ? 1.f : 0.f;
        float fx1 = ((unsigned)x1 < (unsigned)W) ? 1.f : 0.f;
        float fy0 = ((unsigned)y0 < (unsigned)H) ? 1.f : 0.f;
        float fy1 = ((unsigned)y1 < (unsigned)H) ? 1.f : 0.f;
        int xc0 = min(max(x0, 0), W - 1);
        int xc1 = min(max(x1, 0), W - 1);
        int yc0 = min(max(y0, 0), H - 1);
        int yc1 = min(max(y1, 0), H - 1);

        int4 idx;
        idx.x = base + yc0 * W + xc0;
        idx.y = base + yc0 * W + xc1;
        idx.z = base + yc1 * W + xc0;
        idx.w = base + yc1 * W + xc1;
        float4 wv;
        wv.x = aw * wy0 * wx0 * fy0 * fx0;
        wv.y = aw * wy0 * wx1 * fy0 * fx1;
        wv.z = aw * wy1 * wx0 * fy1 * fx0;
        wv.w = aw * wy1 * wx1 * fy1 * fx1;
        sidx[t] = idx;
        sw[t] = wv;
    }
    __syncthreads();

    const int h = t >> 5;
    const int lane = t & 31;
    const __half* vp = valh + h * 32 + lane;

    float acc = 0.f;
#pragma unroll
    for (int p = 0; p < 16; p++) {
        int4 id = sidx[h * 16 + p];
        float4 wv = sw[h * 16 + p];
        acc = fmaf(wv.x, __half2float(vp[(size_t)id.x << 8]), acc);
        acc = fmaf(wv.y, __half2float(vp[(size_t)id.y << 8]), acc);
        acc = fmaf(wv.z, __half2float(vp[(size_t)id.z << 8]), acc);
        acc = fmaf(wv.w, __half2float(vp[(size_t)id.w << 8]), acc);
    }
    outh[(size_t)row * 256 + h * 32 + lane] = __float2half_rn(acc);
}

// ---------------- fused residual add + LayerNorm (C=256), optional fp16 out -----------
template <int SPLIT>
__global__ void __launch_bounds__(256) add_ln(const float* __restrict__ a,
                                              const float* __restrict__ b,
                                              const float* __restrict__ g,
                                              const float* __restrict__ be,
                                              float* __restrict__ out,
                                              __half* __restrict__ oh) {
    int row = blockIdx.x;
    int t = threadIdx.x;
    float v = a[(size_t)row * 256 + t] + b[(size_t)row * 256 + t];

    __shared__ float red[8];
    __shared__ float stat[2];

    float s = v;
#pragma unroll
    for (int o = 16; o; o >>= 1) s += __shfl_xor_sync(0xffffffffu, s, o);
    if ((t & 31) == 0) red[t >> 5] = s;
    __syncthreads();
    if (t == 0) {
        float tot = 0.f;
        for (int i = 0; i < 8; i++) tot += red[i];
        stat[0] = tot * (1.f / 256.f);
    }
    __syncthreads();
    float mean = stat[0];
    float d = v - mean;

    s = d * d;
#pragma unroll
    for (int o = 16; o; o >>= 1) s += __shfl_xor_sync(0xffffffffu, s, o);
    __syncthreads();
    if ((t & 31) == 0) red[t >> 5] = s;
    __syncthreads();
    if (t == 0) {
        float tot = 0.f;
        for (int i = 0; i < 8; i++) tot += red[i];
        stat[1] = tot * (1.f / 256.f);
    }
    __syncthreads();
    float var = stat[1];

    float y = d * rsqrtf(var + 1e-5f) * g[t] + be[t];
    out[(size_t)row * 256 + t] = y;
    if (SPLIT) oh[(size_t)row * 256 + t] = __float2half_rn(y);
}

// ---------------- launch -------------------------------------------------------------
extern "C" void kernel_launch(void* const* d_in, const int* in_sizes, int n_in,
                              void* d_out, int out_size) {
    const float* src   = (const float*)d_in[0];
    const float* pos   = (const float*)d_in[1];
    const float* refp  = (const float*)d_in[2];
    const float* W_off  = (const float*)d_in[5];
    const float* b_off  = (const float*)d_in[6];
    const float* W_attn = (const float*)d_in[7];
    const float* b_attn = (const float*)d_in[8];
    const float* W_val  = (const float*)d_in[9];
    const float* b_val  = (const float*)d_in[10];
    const float* W_out  = (const float*)d_in[11];
    const float* b_out  = (const float*)d_in[12];
    const float* W1     = (const float*)d_in[13];
    const float* b1     = (const float*)d_in[14];
    const float* W2     = (const float*)d_in[15];
    const float* b2     = (const float*)d_in[16];
    const float* g1p    = (const float*)d_in[17];
    const float* be1p   = (const float*)d_in[18];
    const float* g2p    = (const float*)d_in[19];
    const float* be2p   = (const float*)d_in[20];
    float* out = (float*)d_out;

    __half *qh, *sh, *valh, *aoh, *xh, *h1h;
    float *offb, *attn, *src2, *x, *ff, *bqa;
    cudaGetSymbolAddress((void**)&qh, g_qh);     cudaGetSymbolAddress((void**)&sh, g_sh);
    cudaGetSymbolAddress((void**)&offb, g_offb); cudaGetSymbolAddress((void**)&attn, g_attn);
    cudaGetSymbolAddress((void**)&valh, g_valh); cudaGetSymbolAddress((void**)&aoh, g_aoh);
    cudaGetSymbolAddress((void**)&src2, g_src2); cudaGetSymbolAddress((void**)&x, g_x);
    cudaGetSymbolAddress((void**)&xh, g_xh);     cudaGetSymbolAddress((void**)&h1h, g_h1h);
    cudaGetSymbolAddress((void**)&ff, g_ff);     cudaGetSymbolAddress((void**)&bqa, g_bqa);

    __half *wh, *wl;
    cudaGetSymbolAddress((void**)&wh, g_wt_hi);
    cudaGetSymbolAddress((void**)&wl, g_wt_lo);
    __half *qph = wh + 0,      *qpl = wl + 0;        // merged off|attn, N=384
    __half *valw = wh + 98304, *valwl = wl + 98304;
    __half *outh = wh + 163840, *outl = wl + 163840;
    __half *w1h  = wh + 229376, *w1l  = wl + 229376;
    __half *w2h  = wh + 491520, *w2l  = wl + 491520;

    cudaFuncSetAttribute(tgemm<0, 0>, cudaFuncAttributeMaxDynamicSharedMemorySize, SMEM_TOT);
    cudaFuncSetAttribute(tgemm<0, 1>, cudaFuncAttributeMaxDynamicSharedMemorySize, SMEM_TOT);
    cudaFuncSetAttribute(tgemm<1, 1>, cudaFuncAttributeMaxDynamicSharedMemorySize, SMEM_TOT);

    const int M = MTOT;
    const int mby = (M + 127) / 128;   // 208
    const int n4 = M * DM / 4;

    convw_all<<<(WT_TOTAL + 255) / 256, 256>>>(W_off, W_attn, W_val, W_out, W1, W2,
                                               b_off, b_attn, wh, wl, bqa);
    qsplit<<<(n4 + 255) / 256, 256>>>(src, pos, (uint2*)qh, (uint2*)sh, n4);

    // merged qproj: cols 0..255 -> offb, 256..383 -> attn
    tgemm<0, 0><<<dim3(3, mby), 256, SMEM_TOT>>>(qh, qph, qpl, bqa, offb, attn, nullptr, M, 256, 384, 256);
    // value projection -> fp16
    tgemm<0, 1><<<dim3(2, mby), 256, SMEM_TOT>>>(sh, valw, valwl, b_val, nullptr, nullptr, valh, M, 256, 256, 256);

    msda_fused<<<M, 256>>>(refp, offb, attn, valh, aoh);

    tgemm<0, 0><<<dim3(2, mby), 256, SMEM_TOT>>>(aoh, outh, outl, b_out, src2, nullptr, nullptr, M, 256, 256, 256);
    add_ln<1><<<M, 256>>>(src, src2, g1p, be1p, x, xh);

    tgemm<1, 1><<<dim3(8, mby), 256, SMEM_TOT>>>(xh, w1h, w1l, b1, nullptr, nullptr, h1h, M, 256, 1024, 1024);
    tgemm<0, 0><<<dim3(2, mby), 256, SMEM_TOT>>>(h1h, w2h, w2l, b2, ff, nullptr, nullptr, M, 1024, 256, 256);
    add_ln<0><<<M, 256>>>(x, ff, g2p, be2p, out, nullptr);
}

// round 16
// speedup vs baseline: 3.6417x; 1.2472x over previous
#include <cuda_runtime.h>
#include <cuda_fp16.h>
#include <math.h>
#include <cstdint>

#define S_TOTAL 13294
#define BATCHN 2
#define MTOT (BATCHN * S_TOTAL)   // 26588
#define DM 256
#define DF 1024

// ---------------- scratch (static device globals; no runtime allocation) -------------
__device__ __half g_qh[MTOT * DM];     // (src+pos) fp16
__device__ __half g_sh[MTOT * DM];     // src fp16
__device__ float g_offb[MTOT * DM];
__device__ float g_attn[MTOT * 128];
__device__ __half g_valh[MTOT * DM];   // value fp16
__device__ __half g_aoh[MTOT * DM];    // attention output fp16
__device__ float g_src2[MTOT * DM];
__device__ float g_x[MTOT * DM];
__device__ __half g_xh[MTOT * DM];
__device__ __half g_h1h[MTOT * DF];
__device__ float g_ff[MTOT * DM];

// transposed fp16 weights: [N][K] layout
// qproj(off|attn) 384x256 @0; val @98304; out @163840; W1 @229376; W2 @491520
#define WT_TOTAL 753664
__device__ __half g_wt[WT_TOTAL];
__device__ float g_bqa[384];

// ---------------- helpers -------------------------------------------------------------
__device__ __forceinline__ uint32_t smem_u32(const void* p) {
    uint32_t a;
    asm("{ .reg .u64 t; cvta.to.shared.u64 t, %1; cvt.u32.u64 %0, t; }" : "=r"(a) : "l"(p));
    return a;
}
__device__ __forceinline__ void ldsm_x4(uint32_t (&r)[4], uint32_t addr) {
    asm volatile("ldmatrix.sync.aligned.m8n8.x4.shared.b16 {%0,%1,%2,%3}, [%4];"
                 : "=r"(r[0]), "=r"(r[1]), "=r"(r[2]), "=r"(r[3]) : "r"(addr));
}
__device__ __forceinline__ void mma_f16(float (&c)[4], const uint32_t (&a)[4],
                                        uint32_t b0, uint32_t b1) {
    asm volatile("mma.sync.aligned.m16n8k16.row.col.f32.f16.f16.f32 "
                 "{%0,%1,%2,%3}, {%4,%5,%6,%7}, {%8,%9}, {%0,%1,%2,%3};"
                 : "+f"(c[0]), "+f"(c[1]), "+f"(c[2]), "+f"(c[3])
                 : "r"(a[0]), "r"(a[1]), "r"(a[2]), "r"(a[3]), "r"(b0), "r"(b1));
}
__device__ __forceinline__ uint32_t packh(__half a, __half b) {
    return (uint32_t)__half_as_ushort(a) | ((uint32_t)__half_as_ushort(b) << 16);
}
__device__ __forceinline__ void cp16(uint32_t dst, const void* src, bool pred) {
    int sz = pred ? 16 : 0;
    asm volatile("cp.async.cg.shared.global [%0], [%1], 16, %2;"
                 :: "r"(dst), "l"(src), "r"(sz) : "memory");
}
#define CP_COMMIT() asm volatile("cp.async.commit_group;" ::: "memory")
#define CP_WAIT(n)  asm volatile("cp.async.wait_group %0;" :: "n"(n) : "memory")

// ---------------- all weights: transpose + fp16 convert + merged bias -----------------
__global__ void convw_all(const float* __restrict__ W_off, const float* __restrict__ W_attn,
                          const float* __restrict__ W_val, const float* __restrict__ W_out,
                          const float* __restrict__ W1, const float* __restrict__ W2,
                          const float* __restrict__ b_off, const float* __restrict__ b_attn,
                          __half* __restrict__ wt, float* __restrict__ bqa) {
    int i = blockIdx.x * blockDim.x + threadIdx.x;
    if (i < 384) bqa[i] = (i < 256) ? b_off[i] : b_attn[i - 256];
    if (i >= WT_TOTAL) return;
    float x;
    if (i < 98304) {               // qproj merged: N=384, K=256
        int n = i >> 8, k = i & 255;
        x = (n < 256) ? W_off[(size_t)k * 256 + n] : W_attn[(size_t)k * 128 + (n - 256)];
    } else if (i < 163840) {       // val
        int li = i - 98304; int n = li >> 8, k = li & 255;
        x = W_val[(size_t)k * 256 + n];
    } else if (i < 229376) {       // out
        int li = i - 163840; int n = li >> 8, k = li & 255;
        x = W_out[(size_t)k * 256 + n];
    } else if (i < 491520) {       // W1: N=1024, K=256
        int li = i - 229376; int n = li >> 8, k = li & 255;
        x = W1[(size_t)k * 1024 + n];
    } else {                       // W2: N=256, K=1024
        int li = i - 491520; int n = li >> 10, k = li & 1023;
        x = W2[(size_t)k * 256 + n];
    }
    wt[i] = __float2half_rn(x);
}

// ---------------- activation convert: q = src+pos -> fp16, src -> fp16 ----------------
__global__ void qsplit(const float* __restrict__ src, const float* __restrict__ pos,
                       uint2* __restrict__ qh, uint2* __restrict__ sh, int n4) {
    int i = blockIdx.x * blockDim.x + threadIdx.x;
    if (i >= n4) return;
    float4 s = ((const float4*)src)[i];
    float4 p = ((const float4*)pos)[i];
    qh[i] = make_uint2(packh(__float2half_rn(s.x + p.x), __float2half_rn(s.y + p.y)),
                       packh(__float2half_rn(s.z + p.z), __float2half_rn(s.w + p.w)));
    sh[i] = make_uint2(packh(__float2half_rn(s.x), __float2half_rn(s.y)),
                       packh(__float2half_rn(s.z), __float2half_rn(s.w)));
}

// ---------------- fp16 tensor-core GEMM (mma.sync m16n8k16, pure fp16) ----------------
// CTA 128x128, BK=32, 8 warps (2x4), warp tile 64x32. cp.async 4-stage pipeline.
// Output routing: SPLITOUT -> fp16 Ch; else fp32, col<N1 -> Cf, else C2f.
#define SA 40
#define BUF_B   10240           // 128 * SA * 2 bytes
#define STAGE_B 20480           // A + B
#define NSTAGE 4
#define SMEM_TOT (NSTAGE * STAGE_B)   // 81920

template <int RELU, int SPLITOUT>
__global__ void __launch_bounds__(256, 2)
tgemm(const __half* __restrict__ A, const __half* __restrict__ B,
      const float* __restrict__ bias, float* __restrict__ Cf, float* __restrict__ C2f,
      __half* __restrict__ Ch, int M, int K, int N, int N1) {
    extern __shared__ char dsm[];
    const uint32_t sb = smem_u32(dsm);

    const int t = threadIdx.x;
    const int w = t >> 5;
    const int lane = t & 31;
    const int row0 = blockIdx.y * 128;
    const int col0 = blockIdx.x * 128;
    const int wr = (w >> 2) * 64;
    const int wc = (w & 3) * 32;
    const int N2 = N - N1;

    const uint32_t aOff = (uint32_t)(wr * (SA * 2)) + (lane & 15) * (SA * 2) + ((lane >> 4) << 4);
    const uint32_t bOff = (uint32_t)(wc * (SA * 2)) + ((lane & 7) + ((lane >> 4) << 3)) * (SA * 2)
                        + (((lane >> 3) & 1) << 4);

    float acc[4][4][4];
#pragma unroll
    for (int i = 0; i < 4; i++)
#pragma unroll
        for (int j = 0; j < 4; j++)
#pragma unroll
            for (int r = 0; r < 4; r++) acc[i][j][r] = 0.f;

    const int nk = K >> 5;

    auto load_chunk = [&](int ch) {
        const int k0 = ch << 5;
        const uint32_t st = sb + (uint32_t)(ch % NSTAGE) * STAGE_B;
#pragma unroll
        for (int half = 0; half < 2; half++) {
            int q = t + half * 256;
            int r = q >> 2;
            int c8 = (q & 3) << 3;
            uint32_t doff = (uint32_t)(r * (SA * 2) + c8 * 2);
            bool okA = (row0 + r) < M;
            size_t sA = (size_t)(row0 + r) * K + k0 + c8;
            cp16(st + doff, &A[okA ? sA : 0], okA);
            size_t sB = (size_t)(col0 + r) * K + k0 + c8;
            cp16(st + BUF_B + doff, &B[sB], true);
        }
        CP_COMMIT();
    };

    load_chunk(0);
    if (nk > 1) load_chunk(1);
    if (nk > 2) load_chunk(2);
    for (int ch = 0; ch < nk; ++ch) {
        if (ch + 3 < nk) {
            load_chunk(ch + 3);
            CP_WAIT(3);
        } else if (ch + 2 < nk) {
            CP_WAIT(2);
        } else if (ch + 1 < nk) {
            CP_WAIT(1);
        } else {
            CP_WAIT(0);
        }
        __syncthreads();

        const uint32_t st = sb + (uint32_t)(ch % NSTAGE) * STAGE_B;
        const uint32_t uA = st, uB = st + BUF_B;
#pragma unroll
        for (int k16 = 0; k16 < 2; k16++) {
            const uint32_t kb = (uint32_t)(k16 << 5);
            uint32_t aF[4][4];
#pragma unroll
            for (int i = 0; i < 4; i++)
                ldsm_x4(aF[i], uA + aOff + i * (16 * SA * 2) + kb);
#pragma unroll
            for (int jp = 0; jp < 2; jp++) {
                uint32_t bH[4];
                ldsm_x4(bH, uB + bOff + jp * (16 * SA * 2) + kb);
#pragma unroll
                for (int i = 0; i < 4; i++) {
                    mma_f16(acc[i][jp * 2 + 0], aF[i], bH[0], bH[1]);
                    mma_f16(acc[i][jp * 2 + 1], aF[i], bH[2], bH[3]);
                }
            }
        }
        __syncthreads();
    }

    // ---- epilogue
#pragma unroll
    for (int i = 0; i < 4; i++) {
#pragma unroll
        for (int j = 0; j < 4; j++) {
            int col = col0 + wc + j * 8 + (lane & 3) * 2;
            float bx = bias[col], by = bias[col + 1];
            int rowA = row0 + wr + i * 16 + (lane >> 2);
            int rowB = rowA + 8;
            float v0 = acc[i][j][0] + bx, v1 = acc[i][j][1] + by;
            float v2 = acc[i][j][2] + bx, v3 = acc[i][j][3] + by;
            if (RELU) {
                v0 = fmaxf(v0, 0.f); v1 = fmaxf(v1, 0.f);
                v2 = fmaxf(v2, 0.f); v3 = fmaxf(v3, 0.f);
            }
            if (SPLITOUT) {
                if (rowA < M)
                    *(uint32_t*)&Ch[(size_t)rowA * N + col] = packh(__float2half_rn(v0), __float2half_rn(v1));
                if (rowB < M)
                    *(uint32_t*)&Ch[(size_t)rowB * N + col] = packh(__float2half_rn(v2), __float2half_rn(v3));
            } else if (col < N1) {
                if (rowA < M) *(float2*)&Cf[(size_t)rowA * N1 + col] = make_float2(v0, v1);
                if (rowB < M) *(float2*)&Cf[(size_t)rowB * N1 + col] = make_float2(v2, v3);
            } else {
                int c2 = col - N1;
                if (rowA < M) *(float2*)&C2f[(size_t)rowA * N2 + c2] = make_float2(v0, v1);
                if (rowB < M) *(float2*)&C2f[(size_t)rowB * N2 + c2] = make_float2(v2, v3);
            }
        }
    }
}

// ---------------- fused msda: prep in smem + gather -----------------------------------
__global__ void __launch_bounds__(256) msda_fused(
    const float* __restrict__ refp, const float* __restrict__ off,
    const float* __restrict__ attnlog, const __half* __restrict__ valh,
    __half* __restrict__ outh) {
    __shared__ int4   sidx[128];
    __shared__ float4 sw[128];

    const int row = blockIdx.x;
    const int t = threadIdx.x;
    const int n = (row >= S_TOTAL) ? 1 : 0;

    if (t < 128) {
        const int h = t >> 4;       // head
        const int p = t & 15;       // point (lv*4 + pp)
        const int lv = p >> 2;

        float lg = attnlog[(size_t)row * 128 + h * 16 + p];
        float m = lg;
#pragma unroll
        for (int msk = 8; msk; msk >>= 1)
            m = fmaxf(m, __shfl_xor_sync(0xffffffffu, m, msk, 16));
        float e = __expf(lg - m);
        float den = e;
#pragma unroll
        for (int msk = 8; msk; msk >>= 1)
            den += __shfl_xor_sync(0xffffffffu, den, msk, 16);
        float aw = e / den;

        const int H = (lv == 0) ? 100 : (lv == 1) ? 50 : (lv == 2) ? 25 : 13;
        const int W = H;
        const int start = (lv == 0) ? 0 : (lv == 1) ? 10000 : (lv == 2) ? 12500 : 13125;
        const int base = n * S_TOTAL + start;

        float2 o = ((const float2*)(off + (size_t)row * 256 + h * 32))[p];
        float rx = refp[(size_t)row * 8 + lv * 2 + 0];
        float ry = refp[(size_t)row * 8 + lv * 2 + 1];

        float x = (rx + o.x / (float)W) * (float)W - 0.5f;
        float y = (ry + o.y / (float)H) * (float)H - 0.5f;
        float x0f = floorf(x), y0f = floorf(y);
        int x0 = (int)x0f, y0 = (int)y0f;
        int x1 = x0 + 1, y1 = y0 + 1;
        float wx1 = x - x0f, wx0 = 1.f - wx1;
        float wy1 = y - y0f, wy0 = 1.f - wy1;

        float fx0 = ((unsigned)x0 < (unsigned)W) ? 1.f : 0.f;
        float fx1 = ((unsigned)x1 < (unsigned)W) ? 1.f : 0.f;
        float fy0 = ((unsigned)y0 < (unsigned)H) ? 1.f : 0.f;
        float fy1 = ((unsigned)y1 < (unsigned)H) ? 1.f : 0.f;
        int xc0 = min(max(x0, 0), W - 1);
        int xc1 = min(max(x1, 0), W - 1);
        int yc0 = min(max(y0, 0), H - 1);
        int yc1 = min(max(y1, 0), H - 1);

        int4 idx;
        idx.x = base + yc0 * W + xc0;
        idx.y = base + yc0 * W + xc1;
        idx.z = base + yc1 * W + xc0;
        idx.w = base + yc1 * W + xc1;
        float4 wv;
        wv.x = aw * wy0 * wx0 * fy0 * fx0;
        wv.y = aw * wy0 * wx1 * fy0 * fx1;
        wv.z = aw * wy1 * wx0 * fy1 * fx0;
        wv.w = aw * wy1 * wx1 * fy1 * fx1;
        sidx[t] = idx;
        sw[t] = wv;
    }
    __syncthreads();

    const int h = t >> 5;
    const int lane = t & 31;
    const __half* vp = valh + h * 32 + lane;

    float acc = 0.f;
#pragma unroll
    for (int p = 0; p < 16; p++) {
        int4 id = sidx[h * 16 + p];
        float4 wv = sw[h * 16 + p];
        acc = fmaf(wv.x, __half2float(vp[(size_t)id.x << 8]), acc);
        acc = fmaf(wv.y, __half2float(vp[(size_t)id.y << 8]), acc);
        acc = fmaf(wv.z, __half2float(vp[(size_t)id.z << 8]), acc);
        acc = fmaf(wv.w, __half2float(vp[(size_t)id.w << 8]), acc);
    }
    outh[(size_t)row * 256 + h * 32 + lane] = __float2half_rn(acc);
}

// ---------------- fused residual add + LayerNorm (C=256), optional fp16 out -----------
template <int SPLIT>
__global__ void __launch_bounds__(256) add_ln(const float* __restrict__ a,
                                              const float* __restrict__ b,
                                              const float* __restrict__ g,
                                              const float* __restrict__ be,
                                              float* __restrict__ out,
                                              __half* __restrict__ oh) {
    int row = blockIdx.x;
    int t = threadIdx.x;
    float v = a[(size_t)row * 256 + t] + b[(size_t)row * 256 + t];

    __shared__ float red[8];
    __shared__ float stat[2];

    float s = v;
#pragma unroll
    for (int o = 16; o; o >>= 1) s += __shfl_xor_sync(0xffffffffu, s, o);
    if ((t & 31) == 0) red[t >> 5] = s;
    __syncthreads();
    if (t == 0) {
        float tot = 0.f;
        for (int i = 0; i < 8; i++) tot += red[i];
        stat[0] = tot * (1.f / 256.f);
    }
    __syncthreads();
    float mean = stat[0];
    float d = v - mean;

    s = d * d;
#pragma unroll
    for (int o = 16; o; o >>= 1) s += __shfl_xor_sync(0xffffffffu, s, o);
    __syncthreads();
    if ((t & 31) == 0) red[t >> 5] = s;
    __syncthreads();
    if (t == 0) {
        float tot = 0.f;
        for (int i = 0; i < 8; i++) tot += red[i];
        stat[1] = tot * (1.f / 256.f);
    }
    __syncthreads();
    float var = stat[1];

    float y = d * rsqrtf(var + 1e-5f) * g[t] + be[t];
    out[(size_t)row * 256 + t] = y;
    if (SPLIT) oh[(size_t)row * 256 + t] = __float2half_rn(y);
}

// ---------------- launch -------------------------------------------------------------
extern "C" void kernel_launch(void* const* d_in, const int* in_sizes, int n_in,
                              void* d_out, int out_size) {
    const float* src   = (const float*)d_in[0];
    const float* pos   = (const float*)d_in[1];
    const float* refp  = (const float*)d_in[2];
    const float* W_off  = (const float*)d_in[5];
    const float* b_off  = (const float*)d_in[6];
    const float* W_attn = (const float*)d_in[7];
    const float* b_attn = (const float*)d_in[8];
    const float* W_val  = (const float*)d_in[9];
    const float* b_val  = (const float*)d_in[10];
    const float* W_out  = (const float*)d_in[11];
    const float* b_out  = (const float*)d_in[12];
    const float* W1     = (const float*)d_in[13];
    const float* b1     = (const float*)d_in[14];
    const float* W2     = (const float*)d_in[15];
    const float* b2     = (const float*)d_in[16];
    const float* g1p    = (const float*)d_in[17];
    const float* be1p   = (const float*)d_in[18];
    const float* g2p    = (const float*)d_in[19];
    const float* be2p   = (const float*)d_in[20];
    float* out = (float*)d_out;

    __half *qh, *sh, *valh, *aoh, *xh, *h1h;
    float *offb, *attn, *src2, *x, *ff, *bqa;
    cudaGetSymbolAddress((void**)&qh, g_qh);     cudaGetSymbolAddress((void**)&sh, g_sh);
    cudaGetSymbolAddress((void**)&offb, g_offb); cudaGetSymbolAddress((void**)&attn, g_attn);
    cudaGetSymbolAddress((void**)&valh, g_valh); cudaGetSymbolAddress((void**)&aoh, g_aoh);
    cudaGetSymbolAddress((void**)&src2, g_src2); cudaGetSymbolAddress((void**)&x, g_x);
    cudaGetSymbolAddress((void**)&xh, g_xh);     cudaGetSymbolAddress((void**)&h1h, g_h1h);
    cudaGetSymbolAddress((void**)&ff, g_ff);     cudaGetSymbolAddress((void**)&bqa, g_bqa);

    __half *wt;
    cudaGetSymbolAddress((void**)&wt, g_wt);
    __half *qpw = wt + 0;            // merged off|attn, N=384
    __half *valw = wt + 98304;
    __half *outw = wt + 163840;
    __half *w1w  = wt + 229376;
    __half *w2w  = wt + 491520;

    cudaFuncSetAttribute(tgemm<0, 0>, cudaFuncAttributeMaxDynamicSharedMemorySize, SMEM_TOT);
    cudaFuncSetAttribute(tgemm<0, 1>, cudaFuncAttributeMaxDynamicSharedMemorySize, SMEM_TOT);
    cudaFuncSetAttribute(tgemm<1, 1>, cudaFuncAttributeMaxDynamicSharedMemorySize, SMEM_TOT);

    const int M = MTOT;
    const int mby = (M + 127) / 128;   // 208
    const int n4 = M * DM / 4;

    convw_all<<<(WT_TOTAL + 255) / 256, 256>>>(W_off, W_attn, W_val, W_out, W1, W2,
                                               b_off, b_attn, wt, bqa);
    qsplit<<<(n4 + 255) / 256, 256>>>(src, pos, (uint2*)qh, (uint2*)sh, n4);

    // merged qproj: cols 0..255 -> offb, 256..383 -> attn
    tgemm<0, 0><<<dim3(3, mby), 256, SMEM_TOT>>>(qh, qpw, bqa, offb, attn, nullptr, M, 256, 384, 256);
    // value projection -> fp16
    tgemm<0, 1><<<dim3(2, mby), 256, SMEM_TOT>>>(sh, valw, b_val, nullptr, nullptr, valh, M, 256, 256, 256);

    msda_fused<<<M, 256>>>(refp, offb, attn, valh, aoh);

    tgemm<0, 0><<<dim3(2, mby), 256, SMEM_TOT>>>(aoh, outw, b_out, src2, nullptr, nullptr, M, 256, 256, 256);
    add_ln<1><<<M, 256>>>(src, src2, g1p, be1p, x, xh);

    tgemm<1, 1><<<dim3(8, mby), 256, SMEM_TOT>>>(xh, w1w, b1, nullptr, nullptr, h1h, M, 256, 1024, 1024);
    tgemm<0, 0><<<dim3(2, mby), 256, SMEM_TOT>>>(h1h, w2w, b2, ff, nullptr, nullptr, M, 1024, 256, 256);
    add_ln<0><<<M, 256>>>(x, ff, g2p, be2p, out, nullptr);
}